// round 3
// baseline (speedup 1.0000x reference)
#include <cuda_runtime.h>
#include <cstddef>

// ---------------------------------------------------------------------------
// ConvGraphNet (5-layer GCN) on GB300.
// Per layer: relu(A_norm (x @ W) + b), A_norm = D^-1/2 (A + I) D^-1/2.
// A and W commute, so aggregate on the cheaper side:
//   L1: aggregate(F=128) -> GEMM(+bias+relu fused)
//   L2..L5: GEMM -> aggregate (init carries bias + self-loop) -> relu fused
//           into next layer's A-load.
// ---------------------------------------------------------------------------

#define NODES_MAX 50000
#define EDGES_MAX 400000

static __device__ float g_bufA[(size_t)NODES_MAX * 1024];
static __device__ float g_bufB[(size_t)NODES_MAX * 1024];
static __device__ float g_dinv[NODES_MAX];
static __device__ float g_norm[EDGES_MAX];

// ---------------------------- degree / norm --------------------------------

__global__ void k_deg_init(float* __restrict__ deg, int n) {
    int i = blockIdx.x * blockDim.x + threadIdx.x;
    if (i < n) deg[i] = 1.0f;  // self-loop
}

__global__ void k_deg_edges(const int* __restrict__ dst, float* __restrict__ deg, int e) {
    int i = blockIdx.x * blockDim.x + threadIdx.x;
    if (i < e) atomicAdd(&deg[dst[i]], 1.0f);
}

__global__ void k_dinv(float* __restrict__ deg, int n) {
    int i = blockIdx.x * blockDim.x + threadIdx.x;
    if (i < n) deg[i] = rsqrtf(deg[i]);  // deg >= 1 always
}

__global__ void k_norm(const int* __restrict__ src, const int* __restrict__ dst,
                       const float* __restrict__ dinv, float* __restrict__ nrm, int e) {
    int i = blockIdx.x * blockDim.x + threadIdx.x;
    if (i < e) nrm[i] = dinv[src[i]] * dinv[dst[i]];
}

// ---------------------------- aggregation ----------------------------------

// out[i,f] = bias[f] + dinv[i]^2 * X[i,f]   (self-loop term + bias)
__global__ void k_agg_init(const float* __restrict__ X, const float* __restrict__ dinv,
                           const float* __restrict__ bias, float* __restrict__ out,
                           int n, int fshift) {
    size_t idx = (size_t)blockIdx.x * blockDim.x + threadIdx.x;
    size_t total = (size_t)n << fshift;
    if (idx >= total) return;
    int i = (int)(idx >> fshift);
    int f = (int)(idx & (((size_t)1 << fshift) - 1));
    float d = dinv[i];
    float v = d * d * X[idx];
    if (bias) v += bias[f];
    out[idx] = v;
}

// out[dst[e], f] += norm[e] * X[src[e], f]
__global__ void k_agg_edges(const float* __restrict__ X, const int* __restrict__ src,
                            const int* __restrict__ dst, const float* __restrict__ nrm,
                            float* __restrict__ out, int e, int fshift) {
    size_t idx = (size_t)blockIdx.x * blockDim.x + threadIdx.x;
    size_t total = (size_t)e << fshift;
    if (idx >= total) return;
    int ed = (int)(idx >> fshift);
    int f  = (int)(idx & (((size_t)1 << fshift) - 1));
    int F  = 1 << fshift;
    float v = nrm[ed] * X[(size_t)src[ed] * F + f];
    atomicAdd(&out[(size_t)dst[ed] * F + f], v);
}

__global__ void k_relu(float* __restrict__ x, size_t total) {
    size_t idx = (size_t)blockIdx.x * blockDim.x + threadIdx.x;
    if (idx < total) x[idx] = fmaxf(x[idx], 0.0f);
}

// ---------------------------- fp32 SGEMM -----------------------------------
// C[M,N] = op(A[M,K]) @ B[K,N], op = relu if relu_in.
// If fuse: C = relu(C + bias). BM=128 BN=64 BK=16, 256 threads, 8x4/thread.
// Requires K % 16 == 0, N % 64 == 0.

__global__ __launch_bounds__(256)
void k_sgemm(const float* __restrict__ A, const float* __restrict__ B,
             const float* __restrict__ bias, float* __restrict__ C,
             int M, int K, int N, int fuse, int relu_in) {
    const int BM = 128, BN = 64, BK = 16, TM = 8, TN = 4;
    __shared__ float As[BK][BM];
    __shared__ float Bs[BK][BN];

    int tid = threadIdx.x;
    int tx = tid & 15;          // 16 -> 64 cols
    int ty = tid >> 4;          // 16 -> 128 rows
    int row0 = blockIdx.y * BM;
    int col0 = blockIdx.x * BN;

    // A tile: 128 rows x 16 cols = 512 float4; 2 per thread
    int a_row  = tid >> 2;        // 0..63 (+64 for second)
    int a_col4 = (tid & 3) * 4;   // 0,4,8,12
    // B tile: 16 rows x 64 cols = 256 float4; 1 per thread
    int b_row  = tid >> 4;        // 0..15
    int b_col4 = (tid & 15) * 4;

    float acc[TM][TN];
    #pragma unroll
    for (int i = 0; i < TM; i++)
        #pragma unroll
        for (int j = 0; j < TN; j++) acc[i][j] = 0.0f;

    for (int k0 = 0; k0 < K; k0 += BK) {
        #pragma unroll
        for (int l = 0; l < 2; l++) {
            int r = a_row + l * 64;
            int gr = row0 + r;
            float4 v = make_float4(0.f, 0.f, 0.f, 0.f);
            if (gr < M) v = *(const float4*)&A[(size_t)gr * K + k0 + a_col4];
            if (relu_in) {
                v.x = fmaxf(v.x, 0.f); v.y = fmaxf(v.y, 0.f);
                v.z = fmaxf(v.z, 0.f); v.w = fmaxf(v.w, 0.f);
            }
            As[a_col4 + 0][r] = v.x;
            As[a_col4 + 1][r] = v.y;
            As[a_col4 + 2][r] = v.z;
            As[a_col4 + 3][r] = v.w;
        }
        *(float4*)&Bs[b_row][b_col4] =
            *(const float4*)&B[(size_t)(k0 + b_row) * N + col0 + b_col4];
        __syncthreads();

        #pragma unroll
        for (int k = 0; k < BK; k++) {
            float a[TM];
            float4 a0 = *(const float4*)&As[k][ty * TM];
            float4 a1 = *(const float4*)&As[k][ty * TM + 4];
            a[0] = a0.x; a[1] = a0.y; a[2] = a0.z; a[3] = a0.w;
            a[4] = a1.x; a[5] = a1.y; a[6] = a1.z; a[7] = a1.w;
            float4 bv = *(const float4*)&Bs[k][tx * TN];
            float b[TN] = {bv.x, bv.y, bv.z, bv.w};
            #pragma unroll
            for (int i = 0; i < TM; i++)
                #pragma unroll
                for (int j = 0; j < TN; j++)
                    acc[i][j] = fmaf(a[i], b[j], acc[i][j]);
        }
        __syncthreads();
    }

    float4 bvec = make_float4(0.f, 0.f, 0.f, 0.f);
    if (fuse) bvec = *(const float4*)&bias[col0 + tx * TN];
    #pragma unroll
    for (int i = 0; i < TM; i++) {
        int gr = row0 + ty * TM + i;
        if (gr < M) {
            float4 v = make_float4(acc[i][0], acc[i][1], acc[i][2], acc[i][3]);
            if (fuse) {
                v.x = fmaxf(v.x + bvec.x, 0.f);
                v.y = fmaxf(v.y + bvec.y, 0.f);
                v.z = fmaxf(v.z + bvec.z, 0.f);
                v.w = fmaxf(v.w + bvec.w, 0.f);
            }
            *(float4*)&C[(size_t)gr * N + col0 + tx * TN] = v;
        }
    }
}

// L5 matvec: out[i] = dot(relu(X[i, 0:64]), W)   (K=64, N=1)
__global__ void k_matvec64(const float* __restrict__ X, const float* __restrict__ W,
                           float* __restrict__ out, int M) {
    __shared__ float w[64];
    int t = threadIdx.x;
    if (t < 64) w[t] = W[t];
    __syncthreads();
    int i = blockIdx.x * blockDim.x + t;
    if (i < M) {
        const float4* xr = (const float4*)(X + (size_t)i * 64);
        float s = 0.f;
        #pragma unroll
        for (int k = 0; k < 16; k++) {
            float4 v = xr[k];
            s = fmaf(fmaxf(v.x, 0.f), w[4 * k + 0], s);
            s = fmaf(fmaxf(v.y, 0.f), w[4 * k + 1], s);
            s = fmaf(fmaxf(v.z, 0.f), w[4 * k + 2], s);
            s = fmaf(fmaxf(v.w, 0.f), w[4 * k + 3], s);
        }
        out[i] = s;
    }
}

// ---------------------------- launch ---------------------------------------

static inline unsigned blocks_for(size_t total, int threads) {
    return (unsigned)((total + threads - 1) / threads);
}

extern "C" void kernel_launch(void* const* d_in, const int* in_sizes, int n_in,
                              void* d_out, int out_size) {
    const float* x  = (const float*)d_in[0];
    const int*   ei = (const int*)d_in[1];
    const int N = in_sizes[0] / 128;
    const int E = in_sizes[1] / 2;
    const int* src = ei;
    const int* dst = ei + E;
    const float* W1 = (const float*)d_in[2];  const float* b1 = (const float*)d_in[3];
    const float* W2 = (const float*)d_in[4];  const float* b2 = (const float*)d_in[5];
    const float* W3 = (const float*)d_in[6];  const float* b3 = (const float*)d_in[7];
    const float* W4 = (const float*)d_in[8];  const float* b4 = (const float*)d_in[9];
    const float* W5 = (const float*)d_in[10]; const float* b5 = (const float*)d_in[11];
    float* out = (float*)d_out;

    float *bufA, *bufB, *dinv, *nrm;
    cudaGetSymbolAddress((void**)&bufA, g_bufA);
    cudaGetSymbolAddress((void**)&bufB, g_bufB);
    cudaGetSymbolAddress((void**)&dinv, g_dinv);
    cudaGetSymbolAddress((void**)&nrm,  g_norm);

    const int T = 256;

    // degrees + normalization coefficients
    k_deg_init<<<blocks_for(N, T), T>>>(dinv, N);
    k_deg_edges<<<blocks_for(E, T), T>>>(dst, dinv, E);
    k_dinv<<<blocks_for(N, T), T>>>(dinv, N);
    k_norm<<<blocks_for(E, T), T>>>(src, dst, dinv, nrm, E);

    // ---- Layer 1: aggregate x (F=128), then GEMM 128->1024 (+bias+relu) ----
    k_agg_init<<<blocks_for((size_t)N * 128, T), T>>>(x, dinv, nullptr, bufA, N, 7);
    k_agg_edges<<<blocks_for((size_t)E * 128, T), T>>>(x, src, dst, nrm, bufA, E, 7);
    {
        dim3 g(1024 / 64, (N + 127) / 128);
        k_sgemm<<<g, T>>>(bufA, W1, b1, bufB, N, 128, 1024, 1, 0);
    }

    // ---- Layer 2: GEMM 1024->512 (relu on input), aggregate F=512 ----
    {
        dim3 g(512 / 64, (N + 127) / 128);
        k_sgemm<<<g, T>>>(bufB, W2, nullptr, bufA, N, 1024, 512, 0, 0);
    }
    k_agg_init<<<blocks_for((size_t)N * 512, T), T>>>(bufA, dinv, b2, bufB, N, 9);
    k_agg_edges<<<blocks_for((size_t)E * 512, T), T>>>(bufA, src, dst, nrm, bufB, E, 9);
    // relu fused into next GEMM's A-load

    // ---- Layer 3: GEMM 512->256, aggregate F=256 ----
    {
        dim3 g(256 / 64, (N + 127) / 128);
        k_sgemm<<<g, T>>>(bufB, W3, nullptr, bufA, N, 512, 256, 0, 1);
    }
    k_agg_init<<<blocks_for((size_t)N * 256, T), T>>>(bufA, dinv, b3, bufB, N, 8);
    k_agg_edges<<<blocks_for((size_t)E * 256, T), T>>>(bufA, src, dst, nrm, bufB, E, 8);

    // ---- Layer 4: GEMM 256->64, aggregate F=64 ----
    {
        dim3 g(64 / 64, (N + 127) / 128);
        k_sgemm<<<g, T>>>(bufB, W4, nullptr, bufA, N, 256, 64, 0, 1);
    }
    k_agg_init<<<blocks_for((size_t)N * 64, T), T>>>(bufA, dinv, b4, bufB, N, 6);
    k_agg_edges<<<blocks_for((size_t)E * 64, T), T>>>(bufA, src, dst, nrm, bufB, E, 6);

    // ---- Layer 5: matvec 64->1 (relu on input), aggregate F=1 into out ----
    k_matvec64<<<blocks_for(N, T), T>>>(bufB, W5, bufA, N);
    k_agg_init<<<blocks_for(N, T), T>>>(bufA, dinv, b5, out, N, 0);
    k_agg_edges<<<blocks_for(E, T), T>>>(bufA, src, dst, nrm, out, E, 0);
    k_relu<<<blocks_for(N, T), T>>>(out, (size_t)N);
}

// round 4
// speedup vs baseline: 1.0720x; 1.0720x over previous
#include <cuda_runtime.h>
#include <cstddef>

// ---------------------------------------------------------------------------
// ConvGraphNet (5-layer GCN) on GB300.
// Per layer: relu(A_norm (x @ W) + b), A_norm = D^-1/2 (A + I) D^-1/2.
// A and W commute -> aggregate on the cheaper side:
//   L1: aggregate(F=128) -> GEMM(+bias+relu fused)
//   L2..L5: GEMM -> aggregate (init carries bias + self-loop) -> relu fused
//           into next consumer's load.
// R3: 128x128 SGEMM tiles, 8x8/thread, double-buffered smem; float4 agg.
// ---------------------------------------------------------------------------

#define NODES_MAX 50000
#define EDGES_MAX 400000

static __device__ float g_bufA[(size_t)NODES_MAX * 1024];
static __device__ float g_bufB[(size_t)NODES_MAX * 1024];
static __device__ float g_dinv[NODES_MAX];
static __device__ float g_norm[EDGES_MAX];

// ---------------------------- degree / norm --------------------------------

__global__ void k_deg_init(float* __restrict__ deg, int n) {
    int i = blockIdx.x * blockDim.x + threadIdx.x;
    if (i < n) deg[i] = 1.0f;  // self-loop
}

__global__ void k_deg_edges(const int* __restrict__ dst, float* __restrict__ deg, int e) {
    int i = blockIdx.x * blockDim.x + threadIdx.x;
    if (i < e) atomicAdd(&deg[dst[i]], 1.0f);
}

__global__ void k_dinv(float* __restrict__ deg, int n) {
    int i = blockIdx.x * blockDim.x + threadIdx.x;
    if (i < n) deg[i] = rsqrtf(deg[i]);  // deg >= 1 always
}

__global__ void k_norm(const int* __restrict__ src, const int* __restrict__ dst,
                       const float* __restrict__ dinv, float* __restrict__ nrm, int e) {
    int i = blockIdx.x * blockDim.x + threadIdx.x;
    if (i < e) nrm[i] = dinv[src[i]] * dinv[dst[i]];
}

// ---------------------------- aggregation ----------------------------------

// Scalar versions (F == 1)
__global__ void k_agg_init(const float* __restrict__ X, const float* __restrict__ dinv,
                           const float* __restrict__ bias, float* __restrict__ out, int n) {
    int i = blockIdx.x * blockDim.x + threadIdx.x;
    if (i >= n) return;
    float d = dinv[i];
    out[i] = d * d * X[i] + bias[0];
}

__global__ void k_agg_edges(const float* __restrict__ X, const int* __restrict__ src,
                            const int* __restrict__ dst, const float* __restrict__ nrm,
                            float* __restrict__ out, int e) {
    int i = blockIdx.x * blockDim.x + threadIdx.x;
    if (i >= e) return;
    atomicAdd(&out[dst[i]], nrm[i] * X[src[i]]);
}

// float4 versions (F % 4 == 0, F = 4 << fshift4)
// out[i, :] = bias + dinv[i]^2 * X[i, :]
__global__ void k_agg_init_v4(const float4* __restrict__ X, const float* __restrict__ dinv,
                              const float* __restrict__ bias, float4* __restrict__ out,
                              int n, int fshift4) {
    size_t idx = (size_t)blockIdx.x * blockDim.x + threadIdx.x;
    size_t total = (size_t)n << fshift4;
    if (idx >= total) return;
    int i  = (int)(idx >> fshift4);
    int f4 = (int)(idx & (((size_t)1 << fshift4) - 1));
    float d = dinv[i];
    float s = d * d;
    float4 v = X[idx];
    float4 r;
    if (bias) {
        float4 b = ((const float4*)bias)[f4];
        r.x = fmaf(v.x, s, b.x); r.y = fmaf(v.y, s, b.y);
        r.z = fmaf(v.z, s, b.z); r.w = fmaf(v.w, s, b.w);
    } else {
        r.x = v.x * s; r.y = v.y * s; r.z = v.z * s; r.w = v.w * s;
    }
    out[idx] = r;
}

// out[dst[e], :] += norm[e] * X[src[e], :]
__global__ void k_agg_edges_v4(const float4* __restrict__ X, const int* __restrict__ src,
                               const int* __restrict__ dst, const float* __restrict__ nrm,
                               float* __restrict__ out, int e, int fshift4) {
    size_t idx = (size_t)blockIdx.x * blockDim.x + threadIdx.x;
    size_t total = (size_t)e << fshift4;
    if (idx >= total) return;
    int ed = (int)(idx >> fshift4);
    int f4 = (int)(idx & (((size_t)1 << fshift4) - 1));
    float s = nrm[ed];
    float4 v = X[((size_t)src[ed] << fshift4) + f4];
    float* o = out + ((((size_t)dst[ed] << fshift4) + f4) << 2);
    atomicAdd(o + 0, s * v.x);
    atomicAdd(o + 1, s * v.y);
    atomicAdd(o + 2, s * v.z);
    atomicAdd(o + 3, s * v.w);
}

__global__ void k_relu(float* __restrict__ x, size_t total) {
    size_t idx = (size_t)blockIdx.x * blockDim.x + threadIdx.x;
    if (idx < total) x[idx] = fmaxf(x[idx], 0.0f);
}

// ---------------------------- fp32 SGEMM -----------------------------------
// C[M,N] = op(A[M,K]) @ B[K,N], op = relu if relu_in; if fuse: C = relu(C+bias).
// BM=128, BN template (128 or 64), BK=16, TM=TN=8, double-buffered smem.
// Requires K % 16 == 0, N % BN == 0.

template <int BN>
__global__ __launch_bounds__(16 * (BN / 8))
void k_sgemm2(const float* __restrict__ A, const float* __restrict__ B,
              const float* __restrict__ bias, float* __restrict__ C,
              int M, int K, int N, int fuse, int relu_in) {
    const int BM = 128, BK = 16;
    const int THREADS = 16 * (BN / 8);
    const int A_F4 = BM * BK / 4;          // 512
    const int B_F4 = BK * BN / 4;          // 512 or 256
    const int A_PT = A_F4 / THREADS;       // 2 or 4
    const int B_PT = B_F4 / THREADS;       // 2

    __shared__ float As[2][BK][BM];
    __shared__ float Bs[2][BK][BN];

    int tid = threadIdx.x;
    int tx = tid % (BN / 8);
    int ty = tid / (BN / 8);
    int row0 = blockIdx.y * BM;
    int col0 = blockIdx.x * BN;

    const int nk = K / BK;

    float acc[8][8];
    #pragma unroll
    for (int i = 0; i < 8; i++)
        #pragma unroll
        for (int j = 0; j < 8; j++) acc[i][j] = 0.0f;

    float4 pa[A_PT];
    float4 pb[B_PT];

    // ---- load tile 0 ----
    #pragma unroll
    for (int l = 0; l < A_PT; l++) {
        int i = tid + l * THREADS;
        int r = i >> 2;
        int c4 = (i & 3) * 4;
        int gr = row0 + r;
        float4 v = make_float4(0.f, 0.f, 0.f, 0.f);
        if (gr < M) v = *(const float4*)&A[(size_t)gr * K + c4];
        if (relu_in) {
            v.x = fmaxf(v.x, 0.f); v.y = fmaxf(v.y, 0.f);
            v.z = fmaxf(v.z, 0.f); v.w = fmaxf(v.w, 0.f);
        }
        As[0][c4 + 0][r] = v.x; As[0][c4 + 1][r] = v.y;
        As[0][c4 + 2][r] = v.z; As[0][c4 + 3][r] = v.w;
    }
    #pragma unroll
    for (int l = 0; l < B_PT; l++) {
        int i = tid + l * THREADS;
        int r = i / (BN / 4);
        int c4 = (i % (BN / 4)) * 4;
        *(float4*)&Bs[0][r][c4] = *(const float4*)&B[(size_t)r * N + col0 + c4];
    }
    __syncthreads();

    for (int t = 0; t < nk; t++) {
        int p = t & 1;
        int kn = (t + 1) * BK;

        if (t + 1 < nk) {
            #pragma unroll
            for (int l = 0; l < A_PT; l++) {
                int i = tid + l * THREADS;
                int r = i >> 2;
                int c4 = (i & 3) * 4;
                int gr = row0 + r;
                float4 v = make_float4(0.f, 0.f, 0.f, 0.f);
                if (gr < M) v = *(const float4*)&A[(size_t)gr * K + kn + c4];
                if (relu_in) {
                    v.x = fmaxf(v.x, 0.f); v.y = fmaxf(v.y, 0.f);
                    v.z = fmaxf(v.z, 0.f); v.w = fmaxf(v.w, 0.f);
                }
                pa[l] = v;
            }
            #pragma unroll
            for (int l = 0; l < B_PT; l++) {
                int i = tid + l * THREADS;
                int r = i / (BN / 4);
                int c4 = (i % (BN / 4)) * 4;
                pb[l] = *(const float4*)&B[(size_t)(kn + r) * N + col0 + c4];
            }
        }

        #pragma unroll
        for (int k = 0; k < BK; k++) {
            float4 a0 = *(const float4*)&As[p][k][ty * 8];
            float4 a1 = *(const float4*)&As[p][k][ty * 8 + 4];
            float4 b0 = *(const float4*)&Bs[p][k][tx * 8];
            float4 b1 = *(const float4*)&Bs[p][k][tx * 8 + 4];
            float a[8] = {a0.x, a0.y, a0.z, a0.w, a1.x, a1.y, a1.z, a1.w};
            float b[8] = {b0.x, b0.y, b0.z, b0.w, b1.x, b1.y, b1.z, b1.w};
            #pragma unroll
            for (int i = 0; i < 8; i++)
                #pragma unroll
                for (int j = 0; j < 8; j++)
                    acc[i][j] = fmaf(a[i], b[j], acc[i][j]);
        }

        if (t + 1 < nk) {
            int q = 1 - p;
            #pragma unroll
            for (int l = 0; l < A_PT; l++) {
                int i = tid + l * THREADS;
                int r = i >> 2;
                int c4 = (i & 3) * 4;
                As[q][c4 + 0][r] = pa[l].x; As[q][c4 + 1][r] = pa[l].y;
                As[q][c4 + 2][r] = pa[l].z; As[q][c4 + 3][r] = pa[l].w;
            }
            #pragma unroll
            for (int l = 0; l < B_PT; l++) {
                int i = tid + l * THREADS;
                int r = i / (BN / 4);
                int c4 = (i % (BN / 4)) * 4;
                *(float4*)&Bs[q][r][c4] = pb[l];
            }
            __syncthreads();
        }
    }

    // ---- epilogue ----
    float bv[8];
    if (fuse) {
        float4 q0 = *(const float4*)&bias[col0 + tx * 8];
        float4 q1 = *(const float4*)&bias[col0 + tx * 8 + 4];
        bv[0] = q0.x; bv[1] = q0.y; bv[2] = q0.z; bv[3] = q0.w;
        bv[4] = q1.x; bv[5] = q1.y; bv[6] = q1.z; bv[7] = q1.w;
    }
    #pragma unroll
    for (int i = 0; i < 8; i++) {
        int gr = row0 + ty * 8 + i;
        if (gr >= M) continue;
        float4 v0, v1;
        if (fuse) {
            v0 = make_float4(fmaxf(acc[i][0] + bv[0], 0.f), fmaxf(acc[i][1] + bv[1], 0.f),
                             fmaxf(acc[i][2] + bv[2], 0.f), fmaxf(acc[i][3] + bv[3], 0.f));
            v1 = make_float4(fmaxf(acc[i][4] + bv[4], 0.f), fmaxf(acc[i][5] + bv[5], 0.f),
                             fmaxf(acc[i][6] + bv[6], 0.f), fmaxf(acc[i][7] + bv[7], 0.f));
        } else {
            v0 = make_float4(acc[i][0], acc[i][1], acc[i][2], acc[i][3]);
            v1 = make_float4(acc[i][4], acc[i][5], acc[i][6], acc[i][7]);
        }
        *(float4*)&C[(size_t)gr * N + col0 + tx * 8]     = v0;
        *(float4*)&C[(size_t)gr * N + col0 + tx * 8 + 4] = v1;
    }
}

// L5 matvec: out[i] = dot(relu(X[i, 0:64]), W)   (K=64, N=1)
__global__ void k_matvec64(const float* __restrict__ X, const float* __restrict__ W,
                           float* __restrict__ out, int M) {
    __shared__ float w[64];
    int t = threadIdx.x;
    if (t < 64) w[t] = W[t];
    __syncthreads();
    int i = blockIdx.x * blockDim.x + t;
    if (i < M) {
        const float4* xr = (const float4*)(X + (size_t)i * 64);
        float s = 0.f;
        #pragma unroll
        for (int k = 0; k < 16; k++) {
            float4 v = xr[k];
            s = fmaf(fmaxf(v.x, 0.f), w[4 * k + 0], s);
            s = fmaf(fmaxf(v.y, 0.f), w[4 * k + 1], s);
            s = fmaf(fmaxf(v.z, 0.f), w[4 * k + 2], s);
            s = fmaf(fmaxf(v.w, 0.f), w[4 * k + 3], s);
        }
        out[i] = s;
    }
}

// ---------------------------- launch ---------------------------------------

static inline unsigned blocks_for(size_t total, int threads) {
    return (unsigned)((total + threads - 1) / threads);
}

extern "C" void kernel_launch(void* const* d_in, const int* in_sizes, int n_in,
                              void* d_out, int out_size) {
    const float* x  = (const float*)d_in[0];
    const int*   ei = (const int*)d_in[1];
    const int N = in_sizes[0] / 128;
    const int E = in_sizes[1] / 2;
    const int* src = ei;
    const int* dst = ei + E;
    const float* W1 = (const float*)d_in[2];  const float* b1 = (const float*)d_in[3];
    const float* W2 = (const float*)d_in[4];  const float* b2 = (const float*)d_in[5];
    const float* W3 = (const float*)d_in[6];  const float* b3 = (const float*)d_in[7];
    const float* W4 = (const float*)d_in[8];  const float* b4 = (const float*)d_in[9];
    const float* W5 = (const float*)d_in[10]; const float* b5 = (const float*)d_in[11];
    float* out = (float*)d_out;

    float *bufA, *bufB, *dinv, *nrm;
    cudaGetSymbolAddress((void**)&bufA, g_bufA);
    cudaGetSymbolAddress((void**)&bufB, g_bufB);
    cudaGetSymbolAddress((void**)&dinv, g_dinv);
    cudaGetSymbolAddress((void**)&nrm,  g_norm);

    const int T = 256;

    // degrees + normalization coefficients
    k_deg_init<<<blocks_for(N, T), T>>>(dinv, N);
    k_deg_edges<<<blocks_for(E, T), T>>>(dst, dinv, E);
    k_dinv<<<blocks_for(N, T), T>>>(dinv, N);
    k_norm<<<blocks_for(E, T), T>>>(src, dst, dinv, nrm, E);

    // ---- Layer 1: aggregate x (F=128), then GEMM 128->1024 (+bias+relu) ----
    k_agg_init_v4<<<blocks_for((size_t)N * 32, T), T>>>((const float4*)x, dinv, nullptr,
                                                        (float4*)bufA, N, 5);
    k_agg_edges_v4<<<blocks_for((size_t)E * 32, T), T>>>((const float4*)x, src, dst, nrm,
                                                         bufA, E, 5);
    {
        dim3 g(1024 / 128, (N + 127) / 128);
        k_sgemm2<128><<<g, 256>>>(bufA, W1, b1, bufB, N, 128, 1024, 1, 0);
    }

    // ---- Layer 2: GEMM 1024->512, aggregate F=512 ----
    {
        dim3 g(512 / 128, (N + 127) / 128);
        k_sgemm2<128><<<g, 256>>>(bufB, W2, nullptr, bufA, N, 1024, 512, 0, 0);
    }
    k_agg_init_v4<<<blocks_for((size_t)N * 128, T), T>>>((const float4*)bufA, dinv, b2,
                                                         (float4*)bufB, N, 7);
    k_agg_edges_v4<<<blocks_for((size_t)E * 128, T), T>>>((const float4*)bufA, src, dst, nrm,
                                                          bufB, E, 7);
    // relu fused into next GEMM's A-load

    // ---- Layer 3: GEMM 512->256 (relu on input), aggregate F=256 ----
    {
        dim3 g(256 / 128, (N + 127) / 128);
        k_sgemm2<128><<<g, 256>>>(bufB, W3, nullptr, bufA, N, 512, 256, 0, 1);
    }
    k_agg_init_v4<<<blocks_for((size_t)N * 64, T), T>>>((const float4*)bufA, dinv, b3,
                                                        (float4*)bufB, N, 6);
    k_agg_edges_v4<<<blocks_for((size_t)E * 64, T), T>>>((const float4*)bufA, src, dst, nrm,
                                                         bufB, E, 6);

    // ---- Layer 4: GEMM 256->64 (relu on input), aggregate F=64 ----
    {
        dim3 g(64 / 64, (N + 127) / 128);
        k_sgemm2<64><<<g, 128>>>(bufB, W4, nullptr, bufA, N, 256, 64, 0, 1);
    }
    k_agg_init_v4<<<blocks_for((size_t)N * 16, T), T>>>((const float4*)bufA, dinv, b4,
                                                        (float4*)bufB, N, 4);
    k_agg_edges_v4<<<blocks_for((size_t)E * 16, T), T>>>((const float4*)bufA, src, dst, nrm,
                                                         bufB, E, 4);

    // ---- Layer 5: matvec 64->1 (relu on input), aggregate F=1 into out ----
    k_matvec64<<<blocks_for(N, T), T>>>(bufB, W5, bufA, N);
    k_agg_init<<<blocks_for(N, T), T>>>(bufA, dinv, b5, out, N);
    k_agg_edges<<<blocks_for(E, T), T>>>(bufA, src, dst, nrm, out, E);
    k_relu<<<blocks_for(N, T), T>>>(out, (size_t)N);
}

// round 5
// speedup vs baseline: 1.4474x; 1.3502x over previous
#include <cuda_runtime.h>
#include <cstddef>

// ---------------------------------------------------------------------------
// ConvGraphNet (5-layer GCN) on GB300.
// relu(A_norm (x @ W) + b), A_norm = D^-1/2 (A + I) D^-1/2.
// R5: per-call CSR build (incoming edges per node) -> atomic-free fused
//     gather-reduce aggregation (init+bias+self-loop+edges in one pass).
// A and W commute -> aggregate on the cheaper side:
//   L1: aggregate(F=128) -> GEMM(+bias+relu)
//   L2..L5: GEMM -> CSR-aggregate (bias folded) -> relu fused into next load.
// ---------------------------------------------------------------------------

#define NODES_MAX 50000
#define EDGES_MAX 400000

static __device__ float g_bufA[(size_t)NODES_MAX * 1024];
static __device__ float g_bufB[(size_t)NODES_MAX * 1024];
static __device__ float g_dinv[NODES_MAX];
static __device__ int   g_cnt[NODES_MAX];
static __device__ int   g_rows[NODES_MAX + 1];
static __device__ int   g_pos[NODES_MAX];
static __device__ int   g_partial[256];
static __device__ int   g_csr_src[EDGES_MAX];
static __device__ float g_csr_nrm[EDGES_MAX];

// ---------------------------- CSR build ------------------------------------

__global__ void k_zero_cnt(int* __restrict__ cnt, int n) {
    int i = blockIdx.x * blockDim.x + threadIdx.x;
    if (i < n) cnt[i] = 0;
}

__global__ void k_hist(const int* __restrict__ dst, int* __restrict__ cnt, int e) {
    int i = blockIdx.x * blockDim.x + threadIdx.x;
    if (i < e) atomicAdd(&cnt[dst[i]], 1);
}

__global__ void k_dinv(const int* __restrict__ cnt, float* __restrict__ dinv, int n) {
    int i = blockIdx.x * blockDim.x + threadIdx.x;
    if (i < n) dinv[i] = rsqrtf((float)(cnt[i] + 1));  // +1 self-loop
}

// exclusive scan of cnt -> rows, 256-wide blocks, Hillis-Steele in smem
__global__ void k_scan_blk(const int* __restrict__ cnt, int* __restrict__ rows,
                           int* __restrict__ partial, int n) {
    __shared__ int sm[256];
    int t = threadIdx.x;
    int i = blockIdx.x * 256 + t;
    int v = (i < n) ? cnt[i] : 0;
    sm[t] = v;
    __syncthreads();
    #pragma unroll
    for (int off = 1; off < 256; off <<= 1) {
        int x = (t >= off) ? sm[t - off] : 0;
        __syncthreads();
        sm[t] += x;
        __syncthreads();
    }
    if (i < n) rows[i] = sm[t] - v;          // local exclusive
    if (t == 255) partial[blockIdx.x] = sm[255];
}

__global__ void k_scan_top(int* __restrict__ partial, int nb) {
    __shared__ int sm[256];
    int t = threadIdx.x;
    int v = (t < nb) ? partial[t] : 0;
    sm[t] = v;
    __syncthreads();
    #pragma unroll
    for (int off = 1; off < 256; off <<= 1) {
        int x = (t >= off) ? sm[t - off] : 0;
        __syncthreads();
        sm[t] += x;
        __syncthreads();
    }
    if (t < nb) partial[t] = sm[t] - v;      // exclusive
}

__global__ void k_scan_add(int* __restrict__ rows, int* __restrict__ pos,
                           const int* __restrict__ partial, int n, int e_total) {
    int i = blockIdx.x * 256 + threadIdx.x;
    if (i < n) {
        int r = rows[i] + partial[blockIdx.x];
        rows[i] = r;
        pos[i] = r;
    }
    if (i == 0) rows[n] = e_total;
}

__global__ void k_scatter(const int* __restrict__ src, const int* __restrict__ dst,
                          const float* __restrict__ dinv, int* __restrict__ pos,
                          int* __restrict__ csr_src, float* __restrict__ csr_nrm, int e) {
    int i = blockIdx.x * blockDim.x + threadIdx.x;
    if (i >= e) return;
    int s = src[i], d = dst[i];
    int j = atomicAdd(&pos[d], 1);
    csr_src[j] = s;
    csr_nrm[j] = dinv[s] * dinv[d];
}

// ---------------------------- CSR aggregation -------------------------------
// out[i,:] = (bias) + dinv[i]^2 * X[i,:] + sum_j csr_nrm[j] * X[csr_src[j],:]
// F = 4*F4PN floats per node; 256-thread blocks, 256/F4PN nodes per block.

template <int F4PN>
__global__ __launch_bounds__(256)
void k_csr_agg(const float4* __restrict__ X, const int* __restrict__ rows,
               const int* __restrict__ csr_src, const float* __restrict__ csr_nrm,
               const float* __restrict__ dinv, const float* __restrict__ bias,
               float4* __restrict__ out, int n) {
    const int NPB = 256 / F4PN;
    int tid = threadIdx.x;
    int local = tid / F4PN;
    int f4 = tid % F4PN;
    int i = blockIdx.x * NPB + local;
    if (i >= n) return;

    float d = dinv[i];
    float s = d * d;
    size_t base = (size_t)i * F4PN + f4;
    float4 xs = X[base];
    float4 acc;
    acc.x = xs.x * s; acc.y = xs.y * s; acc.z = xs.z * s; acc.w = xs.w * s;
    if (bias) {
        float4 b = ((const float4*)bias)[f4];
        acc.x += b.x; acc.y += b.y; acc.z += b.z; acc.w += b.w;
    }
    int beg = rows[i], end = rows[i + 1];
    for (int j = beg; j < end; j++) {
        float w = csr_nrm[j];
        float4 v = X[(size_t)csr_src[j] * F4PN + f4];
        acc.x = fmaf(w, v.x, acc.x);
        acc.y = fmaf(w, v.y, acc.y);
        acc.z = fmaf(w, v.z, acc.z);
        acc.w = fmaf(w, v.w, acc.w);
    }
    out[base] = acc;
}

// Final scalar layer: out[i] = relu(b5 + dinv^2*mv[i] + sum norm*mv[src])
__global__ void k_out_scalar(const float* __restrict__ mv, const int* __restrict__ rows,
                             const int* __restrict__ csr_src, const float* __restrict__ csr_nrm,
                             const float* __restrict__ dinv, const float* __restrict__ b5,
                             float* __restrict__ out, int n) {
    int i = blockIdx.x * blockDim.x + threadIdx.x;
    if (i >= n) return;
    float d = dinv[i];
    float s = b5[0] + d * d * mv[i];
    int beg = rows[i], end = rows[i + 1];
    for (int j = beg; j < end; j++)
        s = fmaf(csr_nrm[j], mv[csr_src[j]], s);
    out[i] = fmaxf(s, 0.0f);
}

// ---------------------------- fp32 SGEMM -----------------------------------
// C[M,N] = op(A[M,K]) @ B[K,N], op = relu if relu_in; if fuse: C = relu(C+bias).
// BM=128, BN template (128 or 64), BK=16, 8x8/thread, double-buffered smem.

template <int BN>
__global__ __launch_bounds__(16 * (BN / 8))
void k_sgemm2(const float* __restrict__ A, const float* __restrict__ B,
              const float* __restrict__ bias, float* __restrict__ C,
              int M, int K, int N, int fuse, int relu_in) {
    const int BM = 128, BK = 16;
    const int THREADS = 16 * (BN / 8);
    const int A_F4 = BM * BK / 4;
    const int B_F4 = BK * BN / 4;
    const int A_PT = A_F4 / THREADS;
    const int B_PT = B_F4 / THREADS;

    __shared__ float As[2][BK][BM];
    __shared__ float Bs[2][BK][BN];

    int tid = threadIdx.x;
    int tx = tid % (BN / 8);
    int ty = tid / (BN / 8);
    int row0 = blockIdx.y * BM;
    int col0 = blockIdx.x * BN;

    const int nk = K / BK;

    float acc[8][8];
    #pragma unroll
    for (int i = 0; i < 8; i++)
        #pragma unroll
        for (int j = 0; j < 8; j++) acc[i][j] = 0.0f;

    float4 pa[A_PT];
    float4 pb[B_PT];

    #pragma unroll
    for (int l = 0; l < A_PT; l++) {
        int i = tid + l * THREADS;
        int r = i >> 2;
        int c4 = (i & 3) * 4;
        int gr = row0 + r;
        float4 v = make_float4(0.f, 0.f, 0.f, 0.f);
        if (gr < M) v = *(const float4*)&A[(size_t)gr * K + c4];
        if (relu_in) {
            v.x = fmaxf(v.x, 0.f); v.y = fmaxf(v.y, 0.f);
            v.z = fmaxf(v.z, 0.f); v.w = fmaxf(v.w, 0.f);
        }
        As[0][c4 + 0][r] = v.x; As[0][c4 + 1][r] = v.y;
        As[0][c4 + 2][r] = v.z; As[0][c4 + 3][r] = v.w;
    }
    #pragma unroll
    for (int l = 0; l < B_PT; l++) {
        int i = tid + l * THREADS;
        int r = i / (BN / 4);
        int c4 = (i % (BN / 4)) * 4;
        *(float4*)&Bs[0][r][c4] = *(const float4*)&B[(size_t)r * N + col0 + c4];
    }
    __syncthreads();

    for (int t = 0; t < nk; t++) {
        int p = t & 1;
        int kn = (t + 1) * BK;

        if (t + 1 < nk) {
            #pragma unroll
            for (int l = 0; l < A_PT; l++) {
                int i = tid + l * THREADS;
                int r = i >> 2;
                int c4 = (i & 3) * 4;
                int gr = row0 + r;
                float4 v = make_float4(0.f, 0.f, 0.f, 0.f);
                if (gr < M) v = *(const float4*)&A[(size_t)gr * K + kn + c4];
                if (relu_in) {
                    v.x = fmaxf(v.x, 0.f); v.y = fmaxf(v.y, 0.f);
                    v.z = fmaxf(v.z, 0.f); v.w = fmaxf(v.w, 0.f);
                }
                pa[l] = v;
            }
            #pragma unroll
            for (int l = 0; l < B_PT; l++) {
                int i = tid + l * THREADS;
                int r = i / (BN / 4);
                int c4 = (i % (BN / 4)) * 4;
                pb[l] = *(const float4*)&B[(size_t)(kn + r) * N + col0 + c4];
            }
        }

        #pragma unroll
        for (int k = 0; k < BK; k++) {
            float4 a0 = *(const float4*)&As[p][k][ty * 8];
            float4 a1 = *(const float4*)&As[p][k][ty * 8 + 4];
            float4 b0 = *(const float4*)&Bs[p][k][tx * 8];
            float4 b1 = *(const float4*)&Bs[p][k][tx * 8 + 4];
            float a[8] = {a0.x, a0.y, a0.z, a0.w, a1.x, a1.y, a1.z, a1.w};
            float b[8] = {b0.x, b0.y, b0.z, b0.w, b1.x, b1.y, b1.z, b1.w};
            #pragma unroll
            for (int i = 0; i < 8; i++)
                #pragma unroll
                for (int j = 0; j < 8; j++)
                    acc[i][j] = fmaf(a[i], b[j], acc[i][j]);
        }

        if (t + 1 < nk) {
            int q = 1 - p;
            #pragma unroll
            for (int l = 0; l < A_PT; l++) {
                int i = tid + l * THREADS;
                int r = i >> 2;
                int c4 = (i & 3) * 4;
                As[q][c4 + 0][r] = pa[l].x; As[q][c4 + 1][r] = pa[l].y;
                As[q][c4 + 2][r] = pa[l].z; As[q][c4 + 3][r] = pa[l].w;
            }
            #pragma unroll
            for (int l = 0; l < B_PT; l++) {
                int i = tid + l * THREADS;
                int r = i / (BN / 4);
                int c4 = (i % (BN / 4)) * 4;
                *(float4*)&Bs[q][r][c4] = pb[l];
            }
            __syncthreads();
        }
    }

    float bv[8];
    if (fuse) {
        float4 q0 = *(const float4*)&bias[col0 + tx * 8];
        float4 q1 = *(const float4*)&bias[col0 + tx * 8 + 4];
        bv[0] = q0.x; bv[1] = q0.y; bv[2] = q0.z; bv[3] = q0.w;
        bv[4] = q1.x; bv[5] = q1.y; bv[6] = q1.z; bv[7] = q1.w;
    }
    #pragma unroll
    for (int i = 0; i < 8; i++) {
        int gr = row0 + ty * 8 + i;
        if (gr >= M) continue;
        float4 v0, v1;
        if (fuse) {
            v0 = make_float4(fmaxf(acc[i][0] + bv[0], 0.f), fmaxf(acc[i][1] + bv[1], 0.f),
                             fmaxf(acc[i][2] + bv[2], 0.f), fmaxf(acc[i][3] + bv[3], 0.f));
            v1 = make_float4(fmaxf(acc[i][4] + bv[4], 0.f), fmaxf(acc[i][5] + bv[5], 0.f),
                             fmaxf(acc[i][6] + bv[6], 0.f), fmaxf(acc[i][7] + bv[7], 0.f));
        } else {
            v0 = make_float4(acc[i][0], acc[i][1], acc[i][2], acc[i][3]);
            v1 = make_float4(acc[i][4], acc[i][5], acc[i][6], acc[i][7]);
        }
        *(float4*)&C[(size_t)gr * N + col0 + tx * 8]     = v0;
        *(float4*)&C[(size_t)gr * N + col0 + tx * 8 + 4] = v1;
    }
}

// L5 matvec: out[i] = dot(relu(X[i, 0:64]), W)
__global__ void k_matvec64(const float* __restrict__ X, const float* __restrict__ W,
                           float* __restrict__ out, int M) {
    __shared__ float w[64];
    int t = threadIdx.x;
    if (t < 64) w[t] = W[t];
    __syncthreads();
    int i = blockIdx.x * blockDim.x + t;
    if (i < M) {
        const float4* xr = (const float4*)(X + (size_t)i * 64);
        float s = 0.f;
        #pragma unroll
        for (int k = 0; k < 16; k++) {
            float4 v = xr[k];
            s = fmaf(fmaxf(v.x, 0.f), w[4 * k + 0], s);
            s = fmaf(fmaxf(v.y, 0.f), w[4 * k + 1], s);
            s = fmaf(fmaxf(v.z, 0.f), w[4 * k + 2], s);
            s = fmaf(fmaxf(v.w, 0.f), w[4 * k + 3], s);
        }
        out[i] = s;
    }
}

// ---------------------------- launch ---------------------------------------

static inline unsigned blocks_for(size_t total, int threads) {
    return (unsigned)((total + threads - 1) / threads);
}

extern "C" void kernel_launch(void* const* d_in, const int* in_sizes, int n_in,
                              void* d_out, int out_size) {
    const float* x  = (const float*)d_in[0];
    const int*   ei = (const int*)d_in[1];
    const int N = in_sizes[0] / 128;
    const int E = in_sizes[1] / 2;
    const int* src = ei;
    const int* dst = ei + E;
    const float* W1 = (const float*)d_in[2];  const float* b1 = (const float*)d_in[3];
    const float* W2 = (const float*)d_in[4];  const float* b2 = (const float*)d_in[5];
    const float* W3 = (const float*)d_in[6];  const float* b3 = (const float*)d_in[7];
    const float* W4 = (const float*)d_in[8];  const float* b4 = (const float*)d_in[9];
    const float* W5 = (const float*)d_in[10]; const float* b5 = (const float*)d_in[11];
    float* out = (float*)d_out;

    float *bufA, *bufB, *dinv, *csr_nrm;
    int *cnt, *rows, *pos, *partial, *csr_src;
    cudaGetSymbolAddress((void**)&bufA, g_bufA);
    cudaGetSymbolAddress((void**)&bufB, g_bufB);
    cudaGetSymbolAddress((void**)&dinv, g_dinv);
    cudaGetSymbolAddress((void**)&cnt, g_cnt);
    cudaGetSymbolAddress((void**)&rows, g_rows);
    cudaGetSymbolAddress((void**)&pos, g_pos);
    cudaGetSymbolAddress((void**)&partial, g_partial);
    cudaGetSymbolAddress((void**)&csr_src, g_csr_src);
    cudaGetSymbolAddress((void**)&csr_nrm, g_csr_nrm);

    const int T = 256;
    const int nblk = (N + 255) / 256;  // scan blocks (<= 256)

    // ---- CSR build (incoming edges per node) ----
    k_zero_cnt<<<nblk, T>>>(cnt, N);
    k_hist<<<blocks_for(E, T), T>>>(dst, cnt, E);
    k_dinv<<<nblk, T>>>(cnt, dinv, N);
    k_scan_blk<<<nblk, T>>>(cnt, rows, partial, N);
    k_scan_top<<<1, T>>>(partial, nblk);
    k_scan_add<<<nblk, T>>>(rows, pos, partial, N, E);
    k_scatter<<<blocks_for(E, T), T>>>(src, dst, dinv, pos, csr_src, csr_nrm, E);

    // ---- Layer 1: CSR-aggregate x (F=128), then GEMM 128->1024 (+bias+relu) ----
    k_csr_agg<32><<<(N + 7) / 8, 256>>>((const float4*)x, rows, csr_src, csr_nrm,
                                        dinv, nullptr, (float4*)bufA, N);
    {
        dim3 g(1024 / 128, (N + 127) / 128);
        k_sgemm2<128><<<g, 256>>>(bufA, W1, b1, bufB, N, 128, 1024, 1, 0);
    }

    // ---- Layer 2: GEMM 1024->512, CSR-aggregate F=512 (+b2) ----
    {
        dim3 g(512 / 128, (N + 127) / 128);
        k_sgemm2<128><<<g, 256>>>(bufB, W2, nullptr, bufA, N, 1024, 512, 0, 0);
    }
    k_csr_agg<128><<<(N + 1) / 2, 256>>>((const float4*)bufA, rows, csr_src, csr_nrm,
                                         dinv, b2, (float4*)bufB, N);

    // ---- Layer 3: GEMM 512->256 (relu in), CSR-aggregate F=256 (+b3) ----
    {
        dim3 g(256 / 128, (N + 127) / 128);
        k_sgemm2<128><<<g, 256>>>(bufB, W3, nullptr, bufA, N, 512, 256, 0, 1);
    }
    k_csr_agg<64><<<(N + 3) / 4, 256>>>((const float4*)bufA, rows, csr_src, csr_nrm,
                                        dinv, b3, (float4*)bufB, N);

    // ---- Layer 4: GEMM 256->64 (relu in), CSR-aggregate F=64 (+b4) ----
    {
        dim3 g(64 / 64, (N + 127) / 128);
        k_sgemm2<64><<<g, 128>>>(bufB, W4, nullptr, bufA, N, 256, 64, 0, 1);
    }
    k_csr_agg<16><<<(N + 15) / 16, 256>>>((const float4*)bufA, rows, csr_src, csr_nrm,
                                          dinv, b4, (float4*)bufB, N);

    // ---- Layer 5: matvec 64->1 (relu in), scalar CSR-aggregate into out ----
    k_matvec64<<<blocks_for(N, T), T>>>(bufB, W5, bufA, N);
    k_out_scalar<<<nblk, T>>>(bufA, rows, csr_src, csr_nrm, dinv, b5, out, N);
}

// round 10
// speedup vs baseline: 2.9381x; 2.0299x over previous
#include <cuda_runtime.h>
#include <cuda_bf16.h>
#include <cstddef>
#include <cstdint>

// ---------------------------------------------------------------------------
// ConvGraphNet (5-layer GCN) on GB300.
// R10: GEMMs L1-L3 on mma.sync bf16 (hi/lo split x3 -> ~fp32 precision),
//      family-agnostic ISA only (mma.sync/ldmatrix/cp.async — no tcgen05,
//      which the harness's compute_103->sm_103 pass rejects).
// CSR gather-reduce aggregation (atomic-free) from R5.
// ---------------------------------------------------------------------------

#define NODES_MAX 50000
#define EDGES_MAX 400000
#define MPAD_MAX  50048   // 391 * 128

static __device__ float g_bufA[(size_t)NODES_MAX * 1024];
static __device__ float g_bufB[(size_t)NODES_MAX * 1024];
static __device__ float g_dinv[NODES_MAX];
static __device__ int   g_cnt[NODES_MAX];
static __device__ int   g_rows[NODES_MAX + 1];
static __device__ int   g_pos[NODES_MAX];
static __device__ int   g_partial[256];
static __device__ int   g_csr_src[EDGES_MAX];
static __device__ float g_csr_nrm[EDGES_MAX];
static __device__ __nv_bfloat16 g_wthi[1024 * 512];
static __device__ __nv_bfloat16 g_wtlo[1024 * 512];
static __device__ __nv_bfloat16 g_ahi[(size_t)MPAD_MAX * 1024];
static __device__ __nv_bfloat16 g_alo[(size_t)MPAD_MAX * 1024];

// ---------------------------- PTX helpers ----------------------------------

__device__ __forceinline__ uint32_t smem_u32(const void* p) {
    uint32_t a;
    asm("{ .reg .u64 t; cvta.to.shared.u64 t, %1; cvt.u32.u64 %0, t; }"
        : "=r"(a) : "l"(p));
    return a;
}

__device__ __forceinline__ void cpa16(uint32_t s, const void* g) {
    asm volatile("cp.async.cg.shared.global [%0], [%1], 16;" :: "r"(s), "l"(g));
}

__device__ __forceinline__ void ldsm_x4(uint32_t* r, uint32_t addr) {
    asm volatile("ldmatrix.sync.aligned.m8n8.x4.shared.b16 {%0,%1,%2,%3}, [%4];"
                 : "=r"(r[0]), "=r"(r[1]), "=r"(r[2]), "=r"(r[3]) : "r"(addr));
}

__device__ __forceinline__ void mma_bf16(float* d, const uint32_t* a, const uint32_t* b) {
    asm volatile("mma.sync.aligned.m16n8k16.row.col.f32.bf16.bf16.f32 "
                 "{%0,%1,%2,%3}, {%4,%5,%6,%7}, {%8,%9}, {%0,%1,%2,%3};"
                 : "+f"(d[0]), "+f"(d[1]), "+f"(d[2]), "+f"(d[3])
                 : "r"(a[0]), "r"(a[1]), "r"(a[2]), "r"(a[3]), "r"(b[0]), "r"(b[1]));
}

// ---------------------------- CSR build ------------------------------------

__global__ void k_zero_cnt(int* __restrict__ cnt, int n) {
    int i = blockIdx.x * blockDim.x + threadIdx.x;
    if (i < n) cnt[i] = 0;
}

__global__ void k_hist(const int* __restrict__ dst, int* __restrict__ cnt, int e) {
    int i = blockIdx.x * blockDim.x + threadIdx.x;
    if (i < e) atomicAdd(&cnt[dst[i]], 1);
}

__global__ void k_dinv(const int* __restrict__ cnt, float* __restrict__ dinv, int n) {
    int i = blockIdx.x * blockDim.x + threadIdx.x;
    if (i < n) dinv[i] = rsqrtf((float)(cnt[i] + 1));
}

__global__ void k_scan_blk(const int* __restrict__ cnt, int* __restrict__ rows,
                           int* __restrict__ partial, int n) {
    __shared__ int sm[256];
    int t = threadIdx.x;
    int i = blockIdx.x * 256 + t;
    int v = (i < n) ? cnt[i] : 0;
    sm[t] = v;
    __syncthreads();
    #pragma unroll
    for (int off = 1; off < 256; off <<= 1) {
        int x = (t >= off) ? sm[t - off] : 0;
        __syncthreads();
        sm[t] += x;
        __syncthreads();
    }
    if (i < n) rows[i] = sm[t] - v;
    if (t == 255) partial[blockIdx.x] = sm[255];
}

__global__ void k_scan_top(int* __restrict__ partial, int nb) {
    __shared__ int sm[256];
    int t = threadIdx.x;
    int v = (t < nb) ? partial[t] : 0;
    sm[t] = v;
    __syncthreads();
    #pragma unroll
    for (int off = 1; off < 256; off <<= 1) {
        int x = (t >= off) ? sm[t - off] : 0;
        __syncthreads();
        sm[t] += x;
        __syncthreads();
    }
    if (t < nb) partial[t] = sm[t] - v;
}

__global__ void k_scan_add(int* __restrict__ rows, int* __restrict__ pos,
                           const int* __restrict__ partial, int n, int e_total) {
    int i = blockIdx.x * 256 + threadIdx.x;
    if (i < n) {
        int r = rows[i] + partial[blockIdx.x];
        rows[i] = r;
        pos[i] = r;
    }
    if (i == 0) rows[n] = e_total;
}

__global__ void k_scatter(const int* __restrict__ src, const int* __restrict__ dst,
                          const float* __restrict__ dinv, int* __restrict__ pos,
                          int* __restrict__ csr_src, float* __restrict__ csr_nrm, int e) {
    int i = blockIdx.x * blockDim.x + threadIdx.x;
    if (i >= e) return;
    int s = src[i], d = dst[i];
    int j = atomicAdd(&pos[d], 1);
    csr_src[j] = s;
    csr_nrm[j] = dinv[s] * dinv[d];
}

// ---------------------------- CSR aggregation -------------------------------

template <int F4PN>
__global__ __launch_bounds__(256)
void k_csr_agg(const float4* __restrict__ X, const int* __restrict__ rows,
               const int* __restrict__ csr_src, const float* __restrict__ csr_nrm,
               const float* __restrict__ dinv, const float* __restrict__ bias,
               float4* __restrict__ out, int n) {
    const int NPB = 256 / F4PN;
    int tid = threadIdx.x;
    int local = tid / F4PN;
    int f4 = tid % F4PN;
    int i = blockIdx.x * NPB + local;
    if (i >= n) return;

    float d = dinv[i];
    float s = d * d;
    size_t base = (size_t)i * F4PN + f4;
    float4 xs = X[base];
    float4 acc;
    acc.x = xs.x * s; acc.y = xs.y * s; acc.z = xs.z * s; acc.w = xs.w * s;
    if (bias) {
        float4 b = ((const float4*)bias)[f4];
        acc.x += b.x; acc.y += b.y; acc.z += b.z; acc.w += b.w;
    }
    int beg = rows[i], end = rows[i + 1];
    for (int j = beg; j < end; j++) {
        float w = csr_nrm[j];
        float4 v = X[(size_t)csr_src[j] * F4PN + f4];
        acc.x = fmaf(w, v.x, acc.x);
        acc.y = fmaf(w, v.y, acc.y);
        acc.z = fmaf(w, v.z, acc.z);
        acc.w = fmaf(w, v.w, acc.w);
    }
    out[base] = acc;
}

__global__ void k_out_scalar(const float* __restrict__ mv, const int* __restrict__ rows,
                             const int* __restrict__ csr_src, const float* __restrict__ csr_nrm,
                             const float* __restrict__ dinv, const float* __restrict__ b5,
                             float* __restrict__ out, int n) {
    int i = blockIdx.x * blockDim.x + threadIdx.x;
    if (i >= n) return;
    float d = dinv[i];
    float s = b5[0] + d * d * mv[i];
    int beg = rows[i], end = rows[i + 1];
    for (int j = beg; j < end; j++)
        s = fmaf(csr_nrm[j], mv[csr_src[j]], s);
    out[i] = fmaxf(s, 0.0f);
}

// ---------------------- weight transpose + bf16 split ----------------------
// Wt_hi/Wt_lo[n*K + k] from W[k*N + n]

__global__ void k_wt(const float* __restrict__ W, __nv_bfloat16* __restrict__ hi,
                     __nv_bfloat16* __restrict__ lo, int K, int N) {
    int i = blockIdx.x * 256 + threadIdx.x;
    if (i >= N * K) return;
    int n = i / K, k = i - n * K;
    float v = W[(size_t)k * N + n];
    __nv_bfloat16 h = __float2bfloat16(v);
    hi[i] = h;
    lo[i] = __float2bfloat16(v - __bfloat162float(h));
}

// ---------------------- A split: fp32 -> bf16 hi/lo (relu opt, zero pad) ----
// total_valid = M*K (multiple of 4); total_pad = Mpad*K.

__global__ void k_split(const float* __restrict__ X, __nv_bfloat16* __restrict__ hi,
                        __nv_bfloat16* __restrict__ lo, size_t total_valid,
                        size_t total_pad, int relu) {
    size_t i4 = (size_t)blockIdx.x * blockDim.x + threadIdx.x;
    if (i4 * 4 >= total_pad) return;
    float4 v = make_float4(0.f, 0.f, 0.f, 0.f);
    if (i4 * 4 < total_valid) v = ((const float4*)X)[i4];
    if (relu) {
        v.x = fmaxf(v.x, 0.f); v.y = fmaxf(v.y, 0.f);
        v.z = fmaxf(v.z, 0.f); v.w = fmaxf(v.w, 0.f);
    }
    __nv_bfloat162 h0 = __floats2bfloat162_rn(v.x, v.y);
    __nv_bfloat162 h1 = __floats2bfloat162_rn(v.z, v.w);
    float2 f0 = __bfloat1622float2(h0);
    float2 f1 = __bfloat1622float2(h1);
    __nv_bfloat162 l0 = __floats2bfloat162_rn(v.x - f0.x, v.y - f0.y);
    __nv_bfloat162 l1 = __floats2bfloat162_rn(v.z - f1.x, v.w - f1.y);
    uint2 uh; uh.x = *(uint32_t*)&h0; uh.y = *(uint32_t*)&h1;
    uint2 ul; ul.x = *(uint32_t*)&l0; ul.y = *(uint32_t*)&l1;
    ((uint2*)hi)[i4] = uh;
    ((uint2*)lo)[i4] = ul;
}

// ---------------------- mma.sync bf16x3 GEMM --------------------------------
// C[M,N] = A @ W; A given as bf16 hi/lo [Mpad,K] (row-major), W as bf16 hi/lo
// [N][K] (K-major). Block tile 128x128, 8 warps (4m x 2n), warp tile 32x64,
// BK=64, 2-stage cp.async pipeline. fuse: C = relu(C + bias).
// Requires K % 64 == 0, N % 128 == 0, gridDim.y*128 == Mpad.

#define SROW 144                      // smem row stride bytes (72 bf16)
#define SARR (128 * SROW)             // 18432 bytes per array
#define SSTAGE (4 * SARR)             // 73728
#define MMA_SMEM (2 * SSTAGE)         // 147456

__global__ __launch_bounds__(256, 1)
void k_mma_gemm(const __nv_bfloat16* __restrict__ Ah, const __nv_bfloat16* __restrict__ Al,
                const __nv_bfloat16* __restrict__ Bh, const __nv_bfloat16* __restrict__ Bl,
                const float* __restrict__ bias, float* __restrict__ C,
                int M, int K, int N, int fuse) {
    extern __shared__ char smem[];
    const uint32_t sb = smem_u32(smem);
    const int tid = threadIdx.x;
    const int wid = tid >> 5;
    const int lane = tid & 31;
    const int warp_m = wid & 3;        // 4 warps over M
    const int warp_n = wid >> 2;       // 2 warps over N
    const int row0 = blockIdx.y * 128;
    const int col0 = blockIdx.x * 128;
    const int nc = K >> 6;

    const uint32_t offAh = 0, offAl = SARR, offBh = 2 * SARR, offBl = 3 * SARR;

    float acc[2][8][4];
    #pragma unroll
    for (int i = 0; i < 2; i++)
        #pragma unroll
        for (int j = 0; j < 8; j++)
            #pragma unroll
            for (int c = 0; c < 4; c++) acc[i][j][c] = 0.0f;

    // cp.async one 64-wide K-chunk into stage q
    auto issue = [&](int t, int q) {
        size_t k0 = (size_t)t << 6;
        uint32_t st = sb + q * SSTAGE;
        #pragma unroll
        for (int l = 0; l < 4; l++) {
            int idx = tid + l * 256;
            int r = idx >> 3;           // 0..127
            int c = idx & 7;            // 16B chunk within 64 bf16 row
            uint32_t o = (uint32_t)(r * SROW + c * 16);
            size_t ga = (size_t)(row0 + r) * K + k0 + c * 8;
            size_t gb = (size_t)(col0 + r) * K + k0 + c * 8;
            cpa16(st + offAh + o, Ah + ga);
            cpa16(st + offAl + o, Al + ga);
            cpa16(st + offBh + o, Bh + gb);
            cpa16(st + offBl + o, Bl + gb);
        }
        asm volatile("cp.async.commit_group;" ::: "memory");
    };

    issue(0, 0);

    for (int t = 0; t < nc; t++) {
        int p = t & 1;
        if (t + 1 < nc) {
            issue(t + 1, (t + 1) & 1);
            asm volatile("cp.async.wait_group 1;" ::: "memory");
        } else {
            asm volatile("cp.async.wait_group 0;" ::: "memory");
        }
        __syncthreads();

        uint32_t st = sb + p * SSTAGE;
        #pragma unroll
        for (int ks = 0; ks < 4; ks++) {
            // A fragments: 2 m-tiles (16 rows each), hi + lo
            uint32_t ah[2][4], al[2][4];
            {
                uint32_t rr = (uint32_t)(warp_m * 32 + (lane & 15));
                uint32_t cc = (uint32_t)(ks * 16 + ((lane >> 4) << 3));
                #pragma unroll
                for (int mt = 0; mt < 2; mt++) {
                    uint32_t o = (rr + mt * 16) * SROW + cc * 2;
                    ldsm_x4(ah[mt], st + offAh + o);
                    ldsm_x4(al[mt], st + offAl + o);
                }
            }
            // B fragments: 8 n-tiles via 4 x4-loads per polarity
            uint32_t bh[4][4], bl[4][4];
            {
                int j = lane >> 3;
                uint32_t nn = (uint32_t)(warp_n * 64 + ((j >> 1) << 3) + (lane & 7));
                uint32_t kk = (uint32_t)(ks * 16 + ((j & 1) << 3));
                #pragma unroll
                for (int pp = 0; pp < 4; pp++) {
                    uint32_t o = (nn + pp * 16) * SROW + kk * 2;
                    ldsm_x4(bh[pp], st + offBh + o);
                    ldsm_x4(bl[pp], st + offBl + o);
                }
            }
            #pragma unroll
            for (int mt = 0; mt < 2; mt++)
                #pragma unroll
                for (int nt = 0; nt < 8; nt++) {
                    const uint32_t* Bhf = &bh[nt >> 1][(nt & 1) * 2];
                    const uint32_t* Blf = &bl[nt >> 1][(nt & 1) * 2];
                    mma_bf16(acc[mt][nt], ah[mt], Bhf);
                    mma_bf16(acc[mt][nt], ah[mt], Blf);
                    mma_bf16(acc[mt][nt], al[mt], Bhf);
                }
        }
        __syncthreads();
    }

    // ---- epilogue ----
    int gid = lane >> 2, tig = lane & 3;
    #pragma unroll
    for (int mt = 0; mt < 2; mt++) {
        int r0 = row0 + warp_m * 32 + mt * 16 + gid;
        #pragma unroll
        for (int nt = 0; nt < 8; nt++) {
            int cc = col0 + warp_n * 64 + nt * 8 + tig * 2;
            float2 v0 = make_float2(acc[mt][nt][0], acc[mt][nt][1]);
            float2 v1 = make_float2(acc[mt][nt][2], acc[mt][nt][3]);
            if (fuse) {
                float bx = bias[cc], by = bias[cc + 1];
                v0.x = fmaxf(v0.x + bx, 0.f); v0.y = fmaxf(v0.y + by, 0.f);
                v1.x = fmaxf(v1.x + bx, 0.f); v1.y = fmaxf(v1.y + by, 0.f);
            }
            if (r0 < M)     *(float2*)&C[(size_t)r0 * N + cc] = v0;
            if (r0 + 8 < M) *(float2*)&C[(size_t)(r0 + 8) * N + cc] = v1;
        }
    }
}

// ---------------------------- SIMT SGEMM (L4) -------------------------------

template <int BN>
__global__ __launch_bounds__(16 * (BN / 8))
void k_sgemm2(const float* __restrict__ A, const float* __restrict__ B,
              float* __restrict__ C, int M, int K, int N, int relu_in) {
    const int BM = 128, BK = 16;
    const int THREADS = 16 * (BN / 8);
    const int A_PT = (BM * BK / 4) / THREADS;
    const int B_PT = (BK * BN / 4) / THREADS;

    __shared__ float As[2][BK][BM];
    __shared__ float Bs[2][BK][BN];

    int tid = threadIdx.x;
    int tx = tid % (BN / 8);
    int ty = tid / (BN / 8);
    int row0 = blockIdx.y * BM;
    int col0 = blockIdx.x * BN;
    const int nk = K / BK;

    float acc[8][8];
    #pragma unroll
    for (int i = 0; i < 8; i++)
        #pragma unroll
        for (int j = 0; j < 8; j++) acc[i][j] = 0.0f;

    float4 pa[A_PT];
    float4 pb[B_PT];

    #pragma unroll
    for (int l = 0; l < A_PT; l++) {
        int i = tid + l * THREADS;
        int r = i >> 2;
        int c4 = (i & 3) * 4;
        int gr = row0 + r;
        float4 v = make_float4(0.f, 0.f, 0.f, 0.f);
        if (gr < M) v = *(const float4*)&A[(size_t)gr * K + c4];
        if (relu_in) {
            v.x = fmaxf(v.x, 0.f); v.y = fmaxf(v.y, 0.f);
            v.z = fmaxf(v.z, 0.f); v.w = fmaxf(v.w, 0.f);
        }
        As[0][c4 + 0][r] = v.x; As[0][c4 + 1][r] = v.y;
        As[0][c4 + 2][r] = v.z; As[0][c4 + 3][r] = v.w;
    }
    #pragma unroll
    for (int l = 0; l < B_PT; l++) {
        int i = tid + l * THREADS;
        int r = i / (BN / 4);
        int c4 = (i % (BN / 4)) * 4;
        *(float4*)&Bs[0][r][c4] = *(const float4*)&B[(size_t)r * N + col0 + c4];
    }
    __syncthreads();

    for (int t = 0; t < nk; t++) {
        int p = t & 1;
        int kn = (t + 1) * BK;

        if (t + 1 < nk) {
            #pragma unroll
            for (int l = 0; l < A_PT; l++) {
                int i = tid + l * THREADS;
                int r = i >> 2;
                int c4 = (i & 3) * 4;
                int gr = row0 + r;
                float4 v = make_float4(0.f, 0.f, 0.f, 0.f);
                if (gr < M) v = *(const float4*)&A[(size_t)gr * K + kn + c4];
                if (relu_in) {
                    v.x = fmaxf(v.x, 0.f); v.y = fmaxf(v.y, 0.f);
                    v.z = fmaxf(v.z, 0.f); v.w = fmaxf(v.w, 0.f);
                }
                pa[l] = v;
            }
            #pragma unroll
            for (int l = 0; l < B_PT; l++) {
                int i = tid + l * THREADS;
                int r = i / (BN / 4);
                int c4 = (i % (BN / 4)) * 4;
                pb[l] = *(const float4*)&B[(size_t)(kn + r) * N + col0 + c4];
            }
        }

        #pragma unroll
        for (int k = 0; k < BK; k++) {
            float4 a0 = *(const float4*)&As[p][k][ty * 8];
            float4 a1 = *(const float4*)&As[p][k][ty * 8 + 4];
            float4 b0 = *(const float4*)&Bs[p][k][tx * 8];
            float4 b1 = *(const float4*)&Bs[p][k][tx * 8 + 4];
            float a[8] = {a0.x, a0.y, a0.z, a0.w, a1.x, a1.y, a1.z, a1.w};
            float b[8] = {b0.x, b0.y, b0.z, b0.w, b1.x, b1.y, b1.z, b1.w};
            #pragma unroll
            for (int i = 0; i < 8; i++)
                #pragma unroll
                for (int j = 0; j < 8; j++)
                    acc[i][j] = fmaf(a[i], b[j], acc[i][j]);
        }

        if (t + 1 < nk) {
            int q = 1 - p;
            #pragma unroll
            for (int l = 0; l < A_PT; l++) {
                int i = tid + l * THREADS;
                int r = i >> 2;
                int c4 = (i & 3) * 4;
                As[q][c4 + 0][r] = pa[l].x; As[q][c4 + 1][r] = pa[l].y;
                As[q][c4 + 2][r] = pa[l].z; As[q][c4 + 3][r] = pa[l].w;
            }
            #pragma unroll
            for (int l = 0; l < B_PT; l++) {
                int i = tid + l * THREADS;
                int r = i / (BN / 4);
                int c4 = (i % (BN / 4)) * 4;
                *(float4*)&Bs[q][r][c4] = pb[l];
            }
            __syncthreads();
        }
    }

    #pragma unroll
    for (int i = 0; i < 8; i++) {
        int gr = row0 + ty * 8 + i;
        if (gr >= M) continue;
        float4 v0 = make_float4(acc[i][0], acc[i][1], acc[i][2], acc[i][3]);
        float4 v1 = make_float4(acc[i][4], acc[i][5], acc[i][6], acc[i][7]);
        *(float4*)&C[(size_t)gr * N + col0 + tx * 8]     = v0;
        *(float4*)&C[(size_t)gr * N + col0 + tx * 8 + 4] = v1;
    }
}

// L5 matvec
__global__ void k_matvec64(const float* __restrict__ X, const float* __restrict__ W,
                           float* __restrict__ out, int M) {
    __shared__ float w[64];
    int t = threadIdx.x;
    if (t < 64) w[t] = W[t];
    __syncthreads();
    int i = blockIdx.x * blockDim.x + t;
    if (i < M) {
        const float4* xr = (const float4*)(X + (size_t)i * 64);
        float s = 0.f;
        #pragma unroll
        for (int k = 0; k < 16; k++) {
            float4 v = xr[k];
            s = fmaf(fmaxf(v.x, 0.f), w[4 * k + 0], s);
            s = fmaf(fmaxf(v.y, 0.f), w[4 * k + 1], s);
            s = fmaf(fmaxf(v.z, 0.f), w[4 * k + 2], s);
            s = fmaf(fmaxf(v.w, 0.f), w[4 * k + 3], s);
        }
        out[i] = s;
    }
}

// ---------------------------- launch ---------------------------------------

static inline unsigned blocks_for(size_t total, int threads) {
    return (unsigned)((total + threads - 1) / threads);
}

extern "C" void kernel_launch(void* const* d_in, const int* in_sizes, int n_in,
                              void* d_out, int out_size) {
    const float* x  = (const float*)d_in[0];
    const int*   ei = (const int*)d_in[1];
    const int N = in_sizes[0] / 128;
    const int E = in_sizes[1] / 2;
    const int* src = ei;
    const int* dst = ei + E;
    const float* W1 = (const float*)d_in[2];  const float* b1 = (const float*)d_in[3];
    const float* W2 = (const float*)d_in[4];  const float* b2 = (const float*)d_in[5];
    const float* W3 = (const float*)d_in[6];  const float* b3 = (const float*)d_in[7];
    const float* W4 = (const float*)d_in[8];  const float* b4 = (const float*)d_in[9];
    const float* W5 = (const float*)d_in[10]; const float* b5 = (const float*)d_in[11];
    float* out = (float*)d_out;

    float *bufA, *bufB, *dinv, *csr_nrm;
    int *cnt, *rows, *pos, *partial, *csr_src;
    __nv_bfloat16 *wthi, *wtlo, *ahi, *alo;
    cudaGetSymbolAddress((void**)&bufA, g_bufA);
    cudaGetSymbolAddress((void**)&bufB, g_bufB);
    cudaGetSymbolAddress((void**)&dinv, g_dinv);
    cudaGetSymbolAddress((void**)&cnt, g_cnt);
    cudaGetSymbolAddress((void**)&rows, g_rows);
    cudaGetSymbolAddress((void**)&pos, g_pos);
    cudaGetSymbolAddress((void**)&partial, g_partial);
    cudaGetSymbolAddress((void**)&csr_src, g_csr_src);
    cudaGetSymbolAddress((void**)&csr_nrm, g_csr_nrm);
    cudaGetSymbolAddress((void**)&wthi, g_wthi);
    cudaGetSymbolAddress((void**)&wtlo, g_wtlo);
    cudaGetSymbolAddress((void**)&ahi, g_ahi);
    cudaGetSymbolAddress((void**)&alo, g_alo);

    cudaFuncSetAttribute(k_mma_gemm, cudaFuncAttributeMaxDynamicSharedMemorySize,
                         MMA_SMEM);

    const int T = 256;
    const int nblk = (N + 255) / 256;
    const int mtiles = (N + 127) / 128;
    const size_t Mpad = (size_t)mtiles * 128;

    // ---- CSR build ----
    k_zero_cnt<<<nblk, T>>>(cnt, N);
    k_hist<<<blocks_for(E, T), T>>>(dst, cnt, E);
    k_dinv<<<nblk, T>>>(cnt, dinv, N);
    k_scan_blk<<<nblk, T>>>(cnt, rows, partial, N);
    k_scan_top<<<1, T>>>(partial, nblk);
    k_scan_add<<<nblk, T>>>(rows, pos, partial, N, E);
    k_scatter<<<blocks_for(E, T), T>>>(src, dst, dinv, pos, csr_src, csr_nrm, E);

    // ---- Layer 1: aggregate x (F=128) -> mma GEMM 128->1024 (+b1,relu) ----
    k_csr_agg<32><<<(N + 7) / 8, 256>>>((const float4*)x, rows, csr_src, csr_nrm,
                                        dinv, nullptr, (float4*)bufA, N);
    k_wt<<<blocks_for(1024 * 128, T), T>>>(W1, wthi, wtlo, 128, 1024);
    k_split<<<blocks_for(Mpad * 128 / 4, T), T>>>(bufA, ahi, alo,
                                                  (size_t)N * 128, Mpad * 128, 0);
    k_mma_gemm<<<dim3(1024 / 128, mtiles), 256, MMA_SMEM>>>(
        ahi, alo, wthi, wtlo, b1, bufB, N, 128, 1024, 1);

    // ---- Layer 2: mma GEMM 1024->512, CSR-aggregate (+b2) ----
    k_wt<<<blocks_for(512 * 1024, T), T>>>(W2, wthi, wtlo, 1024, 512);
    k_split<<<blocks_for(Mpad * 1024 / 4, T), T>>>(bufB, ahi, alo,
                                                   (size_t)N * 1024, Mpad * 1024, 0);
    k_mma_gemm<<<dim3(512 / 128, mtiles), 256, MMA_SMEM>>>(
        ahi, alo, wthi, wtlo, nullptr, bufA, N, 1024, 512, 0);
    k_csr_agg<128><<<(N + 1) / 2, 256>>>((const float4*)bufA, rows, csr_src, csr_nrm,
                                         dinv, b2, (float4*)bufB, N);

    // ---- Layer 3: mma GEMM 512->256 (relu in split), CSR-aggregate (+b3) ----
    k_wt<<<blocks_for(256 * 512, T), T>>>(W3, wthi, wtlo, 512, 256);
    k_split<<<blocks_for(Mpad * 512 / 4, T), T>>>(bufB, ahi, alo,
                                                  (size_t)N * 512, Mpad * 512, 1);
    k_mma_gemm<<<dim3(256 / 128, mtiles), 256, MMA_SMEM>>>(
        ahi, alo, wthi, wtlo, nullptr, bufA, N, 512, 256, 0);
    k_csr_agg<64><<<(N + 3) / 4, 256>>>((const float4*)bufA, rows, csr_src, csr_nrm,
                                        dinv, b3, (float4*)bufB, N);

    // ---- Layer 4: SIMT GEMM 256->64 (relu in), CSR-aggregate (+b4) ----
    {
        dim3 g(64 / 64, mtiles);
        k_sgemm2<64><<<g, 128>>>(bufB, W4, bufA, N, 256, 64, 1);
    }
    k_csr_agg<16><<<(N + 15) / 16, 256>>>((const float4*)bufA, rows, csr_src, csr_nrm,
                                          dinv, b4, (float4*)bufB, N);

    // ---- Layer 5: matvec 64->1 (relu in), scalar CSR-aggregate into out ----
    k_matvec64<<<blocks_for(N, T), T>>>(bufB, W5, bufA, N);
    k_out_scalar<<<nblk, T>>>(bufA, rows, csr_src, csr_nrm, dinv, b5, out, N);
}

// round 11
// speedup vs baseline: 3.1282x; 1.0647x over previous
#include <cuda_runtime.h>
#include <cuda_bf16.h>
#include <cstddef>
#include <cstdint>

// ---------------------------------------------------------------------------
// ConvGraphNet (5-layer GCN) on GB300.
// R11: mma.sync bf16x3 GEMMs (R10) + split fused into producers:
//   - CSR aggregation can emit bf16 hi/lo directly (bias/relu fused)
//   - L1 GEMM epilogue emits bf16 hi/lo (bias+relu fused)
//   -> standalone k_split passes eliminated (~660 MB traffic).
// ---------------------------------------------------------------------------

#define NODES_MAX 50000
#define EDGES_MAX 400000
#define MPAD_MAX  50048   // 391 * 128

static __device__ float g_bufA[(size_t)NODES_MAX * 1024];
static __device__ float g_bufB[(size_t)NODES_MAX * 1024];
static __device__ float g_dinv[NODES_MAX];
static __device__ int   g_cnt[NODES_MAX];
static __device__ int   g_rows[NODES_MAX + 1];
static __device__ int   g_pos[NODES_MAX];
static __device__ int   g_partial[256];
static __device__ int   g_csr_src[EDGES_MAX];
static __device__ float g_csr_nrm[EDGES_MAX];
static __device__ __nv_bfloat16 g_wthi[1024 * 512];
static __device__ __nv_bfloat16 g_wtlo[1024 * 512];
// A-operand hi/lo buffers: pair A (L1 input K=128 / L3 input K=512),
// pair B (L2 input K=1024)
static __device__ __nv_bfloat16 g_ahi[(size_t)MPAD_MAX * 512];
static __device__ __nv_bfloat16 g_alo[(size_t)MPAD_MAX * 512];
static __device__ __nv_bfloat16 g_bhi[(size_t)MPAD_MAX * 1024];
static __device__ __nv_bfloat16 g_blo[(size_t)MPAD_MAX * 1024];

// ---------------------------- PTX helpers ----------------------------------

__device__ __forceinline__ uint32_t smem_u32(const void* p) {
    uint32_t a;
    asm("{ .reg .u64 t; cvta.to.shared.u64 t, %1; cvt.u32.u64 %0, t; }"
        : "=r"(a) : "l"(p));
    return a;
}

__device__ __forceinline__ void cpa16(uint32_t s, const void* g) {
    asm volatile("cp.async.cg.shared.global [%0], [%1], 16;" :: "r"(s), "l"(g));
}

__device__ __forceinline__ void ldsm_x4(uint32_t* r, uint32_t addr) {
    asm volatile("ldmatrix.sync.aligned.m8n8.x4.shared.b16 {%0,%1,%2,%3}, [%4];"
                 : "=r"(r[0]), "=r"(r[1]), "=r"(r[2]), "=r"(r[3]) : "r"(addr));
}

__device__ __forceinline__ void mma_bf16(float* d, const uint32_t* a, const uint32_t* b) {
    asm volatile("mma.sync.aligned.m16n8k16.row.col.f32.bf16.bf16.f32 "
                 "{%0,%1,%2,%3}, {%4,%5,%6,%7}, {%8,%9}, {%0,%1,%2,%3};"
                 : "+f"(d[0]), "+f"(d[1]), "+f"(d[2]), "+f"(d[3])
                 : "r"(a[0]), "r"(a[1]), "r"(a[2]), "r"(a[3]), "r"(b[0]), "r"(b[1]));
}

// split a float2 into bf16 hi/lo packed words
__device__ __forceinline__ void split2(float x, float y, uint32_t& h, uint32_t& l) {
    __nv_bfloat162 hb = __floats2bfloat162_rn(x, y);
    float2 hf = __bfloat1622float2(hb);
    __nv_bfloat162 lb = __floats2bfloat162_rn(x - hf.x, y - hf.y);
    h = *(uint32_t*)&hb;
    l = *(uint32_t*)&lb;
}

// ---------------------------- CSR build ------------------------------------

__global__ void k_zero_cnt(int* __restrict__ cnt, int n) {
    int i = blockIdx.x * blockDim.x + threadIdx.x;
    if (i < n) cnt[i] = 0;
}

__global__ void k_hist(const int* __restrict__ dst, int* __restrict__ cnt, int e) {
    int i = blockIdx.x * blockDim.x + threadIdx.x;
    if (i < e) atomicAdd(&cnt[dst[i]], 1);
}

__global__ void k_dinv(const int* __restrict__ cnt, float* __restrict__ dinv, int n) {
    int i = blockIdx.x * blockDim.x + threadIdx.x;
    if (i < n) dinv[i] = rsqrtf((float)(cnt[i] + 1));
}

__global__ void k_scan_blk(const int* __restrict__ cnt, int* __restrict__ rows,
                           int* __restrict__ partial, int n) {
    __shared__ int sm[256];
    int t = threadIdx.x;
    int i = blockIdx.x * 256 + t;
    int v = (i < n) ? cnt[i] : 0;
    sm[t] = v;
    __syncthreads();
    #pragma unroll
    for (int off = 1; off < 256; off <<= 1) {
        int x = (t >= off) ? sm[t - off] : 0;
        __syncthreads();
        sm[t] += x;
        __syncthreads();
    }
    if (i < n) rows[i] = sm[t] - v;
    if (t == 255) partial[blockIdx.x] = sm[255];
}

__global__ void k_scan_top(int* __restrict__ partial, int nb) {
    __shared__ int sm[256];
    int t = threadIdx.x;
    int v = (t < nb) ? partial[t] : 0;
    sm[t] = v;
    __syncthreads();
    #pragma unroll
    for (int off = 1; off < 256; off <<= 1) {
        int x = (t >= off) ? sm[t - off] : 0;
        __syncthreads();
        sm[t] += x;
        __syncthreads();
    }
    if (t < nb) partial[t] = sm[t] - v;
}

__global__ void k_scan_add(int* __restrict__ rows, int* __restrict__ pos,
                           const int* __restrict__ partial, int n, int e_total) {
    int i = blockIdx.x * 256 + threadIdx.x;
    if (i < n) {
        int r = rows[i] + partial[blockIdx.x];
        rows[i] = r;
        pos[i] = r;
    }
    if (i == 0) rows[n] = e_total;
}

__global__ void k_scatter(const int* __restrict__ src, const int* __restrict__ dst,
                          const float* __restrict__ dinv, int* __restrict__ pos,
                          int* __restrict__ csr_src, float* __restrict__ csr_nrm, int e) {
    int i = blockIdx.x * blockDim.x + threadIdx.x;
    if (i >= e) return;
    int s = src[i], d = dst[i];
    int j = atomicAdd(&pos[d], 1);
    csr_src[j] = s;
    csr_nrm[j] = dinv[s] * dinv[d];
}

// zero pad rows of hi/lo arrays: uint2 (4 bf16) granularity
__global__ void k_zero_pad(uint2* __restrict__ hi, uint2* __restrict__ lo,
                           size_t start4, size_t n4) {
    size_t i = (size_t)blockIdx.x * blockDim.x + threadIdx.x;
    if (i < n4) {
        hi[start4 + i] = make_uint2(0, 0);
        lo[start4 + i] = make_uint2(0, 0);
    }
}

// ---------------------------- CSR aggregation -------------------------------

// fp32-out version
template <int F4PN>
__global__ __launch_bounds__(256)
void k_csr_agg(const float4* __restrict__ X, const int* __restrict__ rows,
               const int* __restrict__ csr_src, const float* __restrict__ csr_nrm,
               const float* __restrict__ dinv, const float* __restrict__ bias,
               float4* __restrict__ out, int n) {
    const int NPB = 256 / F4PN;
    int tid = threadIdx.x;
    int local = tid / F4PN;
    int f4 = tid % F4PN;
    int i = blockIdx.x * NPB + local;
    if (i >= n) return;

    float d = dinv[i];
    float s = d * d;
    size_t base = (size_t)i * F4PN + f4;
    float4 xs = X[base];
    float4 acc;
    acc.x = xs.x * s; acc.y = xs.y * s; acc.z = xs.z * s; acc.w = xs.w * s;
    if (bias) {
        float4 b = ((const float4*)bias)[f4];
        acc.x += b.x; acc.y += b.y; acc.z += b.z; acc.w += b.w;
    }
    int beg = rows[i], end = rows[i + 1];
    for (int j = beg; j < end; j++) {
        float w = csr_nrm[j];
        float4 v = X[(size_t)csr_src[j] * F4PN + f4];
        acc.x = fmaf(w, v.x, acc.x);
        acc.y = fmaf(w, v.y, acc.y);
        acc.z = fmaf(w, v.z, acc.z);
        acc.w = fmaf(w, v.w, acc.w);
    }
    out[base] = acc;
}

// bf16 hi/lo-out version (optional bias/relu fused). hi/lo as uint2 = 4 bf16.
template <int F4PN, int RELU>
__global__ __launch_bounds__(256)
void k_csr_agg_split(const float4* __restrict__ X, const int* __restrict__ rows,
                     const int* __restrict__ csr_src, const float* __restrict__ csr_nrm,
                     const float* __restrict__ dinv, const float* __restrict__ bias,
                     uint2* __restrict__ hi, uint2* __restrict__ lo, int n) {
    const int NPB = 256 / F4PN;
    int tid = threadIdx.x;
    int local = tid / F4PN;
    int f4 = tid % F4PN;
    int i = blockIdx.x * NPB + local;
    if (i >= n) return;

    float d = dinv[i];
    float s = d * d;
    size_t base = (size_t)i * F4PN + f4;
    float4 xs = X[base];
    float4 acc;
    acc.x = xs.x * s; acc.y = xs.y * s; acc.z = xs.z * s; acc.w = xs.w * s;
    if (bias) {
        float4 b = ((const float4*)bias)[f4];
        acc.x += b.x; acc.y += b.y; acc.z += b.z; acc.w += b.w;
    }
    int beg = rows[i], end = rows[i + 1];
    for (int j = beg; j < end; j++) {
        float w = csr_nrm[j];
        float4 v = X[(size_t)csr_src[j] * F4PN + f4];
        acc.x = fmaf(w, v.x, acc.x);
        acc.y = fmaf(w, v.y, acc.y);
        acc.z = fmaf(w, v.z, acc.z);
        acc.w = fmaf(w, v.w, acc.w);
    }
    if (RELU) {
        acc.x = fmaxf(acc.x, 0.f); acc.y = fmaxf(acc.y, 0.f);
        acc.z = fmaxf(acc.z, 0.f); acc.w = fmaxf(acc.w, 0.f);
    }
    uint2 uh, ul;
    split2(acc.x, acc.y, uh.x, ul.x);
    split2(acc.z, acc.w, uh.y, ul.y);
    hi[base] = uh;
    lo[base] = ul;
}

__global__ void k_out_scalar(const float* __restrict__ mv, const int* __restrict__ rows,
                             const int* __restrict__ csr_src, const float* __restrict__ csr_nrm,
                             const float* __restrict__ dinv, const float* __restrict__ b5,
                             float* __restrict__ out, int n) {
    int i = blockIdx.x * blockDim.x + threadIdx.x;
    if (i >= n) return;
    float d = dinv[i];
    float s = b5[0] + d * d * mv[i];
    int beg = rows[i], end = rows[i + 1];
    for (int j = beg; j < end; j++)
        s = fmaf(csr_nrm[j], mv[csr_src[j]], s);
    out[i] = fmaxf(s, 0.0f);
}

// ---------------------- weight transpose + bf16 split ----------------------

__global__ void k_wt(const float* __restrict__ W, __nv_bfloat16* __restrict__ hi,
                     __nv_bfloat16* __restrict__ lo, int K, int N) {
    int i = blockIdx.x * 256 + threadIdx.x;
    if (i >= N * K) return;
    int n = i / K, k = i - n * K;
    float v = W[(size_t)k * N + n];
    __nv_bfloat16 h = __float2bfloat16(v);
    hi[i] = h;
    lo[i] = __float2bfloat16(v - __bfloat162float(h));
}

// ---------------------- mma.sync bf16x3 GEMM --------------------------------
// C = A @ W; A bf16 hi/lo [Mpad,K] row-major; W bf16 hi/lo [N][K] K-major.
// Block 128x128, 8 warps (4m x 2n), warp 32x64, BK=64, 2-stage cp.async.
// mode 0: fp32 out (C). mode 2: bf16 hi/lo out (Chi/Clo) with bias+relu.

#define SROW 144
#define SARR (128 * SROW)
#define SSTAGE (4 * SARR)
#define MMA_SMEM (2 * SSTAGE)

__global__ __launch_bounds__(256, 1)
void k_mma_gemm(const __nv_bfloat16* __restrict__ Ah, const __nv_bfloat16* __restrict__ Al,
                const __nv_bfloat16* __restrict__ Bh, const __nv_bfloat16* __restrict__ Bl,
                const float* __restrict__ bias, float* __restrict__ C,
                __nv_bfloat16* __restrict__ Chi, __nv_bfloat16* __restrict__ Clo,
                int M, int K, int N, int mode) {
    extern __shared__ char smem[];
    const uint32_t sb = smem_u32(smem);
    const int tid = threadIdx.x;
    const int wid = tid >> 5;
    const int lane = tid & 31;
    const int warp_m = wid & 3;
    const int warp_n = wid >> 2;
    const int row0 = blockIdx.y * 128;
    const int col0 = blockIdx.x * 128;
    const int nc = K >> 6;

    const uint32_t offAh = 0, offAl = SARR, offBh = 2 * SARR, offBl = 3 * SARR;

    float acc[2][8][4];
    #pragma unroll
    for (int i = 0; i < 2; i++)
        #pragma unroll
        for (int j = 0; j < 8; j++)
            #pragma unroll
            for (int c = 0; c < 4; c++) acc[i][j][c] = 0.0f;

    auto issue = [&](int t, int q) {
        size_t k0 = (size_t)t << 6;
        uint32_t st = sb + q * SSTAGE;
        #pragma unroll
        for (int l = 0; l < 4; l++) {
            int idx = tid + l * 256;
            int r = idx >> 3;
            int c = idx & 7;
            uint32_t o = (uint32_t)(r * SROW + c * 16);
            size_t ga = (size_t)(row0 + r) * K + k0 + c * 8;
            size_t gb = (size_t)(col0 + r) * K + k0 + c * 8;
            cpa16(st + offAh + o, Ah + ga);
            cpa16(st + offAl + o, Al + ga);
            cpa16(st + offBh + o, Bh + gb);
            cpa16(st + offBl + o, Bl + gb);
        }
        asm volatile("cp.async.commit_group;" ::: "memory");
    };

    issue(0, 0);

    for (int t = 0; t < nc; t++) {
        int p = t & 1;
        if (t + 1 < nc) {
            issue(t + 1, (t + 1) & 1);
            asm volatile("cp.async.wait_group 1;" ::: "memory");
        } else {
            asm volatile("cp.async.wait_group 0;" ::: "memory");
        }
        __syncthreads();

        uint32_t st = sb + p * SSTAGE;
        #pragma unroll
        for (int ks = 0; ks < 4; ks++) {
            uint32_t ah[2][4], al[2][4];
            {
                uint32_t rr = (uint32_t)(warp_m * 32 + (lane & 15));
                uint32_t cc = (uint32_t)(ks * 16 + ((lane >> 4) << 3));
                #pragma unroll
                for (int mt = 0; mt < 2; mt++) {
                    uint32_t o = (rr + mt * 16) * SROW + cc * 2;
                    ldsm_x4(ah[mt], st + offAh + o);
                    ldsm_x4(al[mt], st + offAl + o);
                }
            }
            uint32_t bh[4][4], bl[4][4];
            {
                int j = lane >> 3;
                uint32_t nn = (uint32_t)(warp_n * 64 + ((j >> 1) << 3) + (lane & 7));
                uint32_t kk = (uint32_t)(ks * 16 + ((j & 1) << 3));
                #pragma unroll
                for (int pp = 0; pp < 4; pp++) {
                    uint32_t o = (nn + pp * 16) * SROW + kk * 2;
                    ldsm_x4(bh[pp], st + offBh + o);
                    ldsm_x4(bl[pp], st + offBl + o);
                }
            }
            #pragma unroll
            for (int mt = 0; mt < 2; mt++)
                #pragma unroll
                for (int nt = 0; nt < 8; nt++) {
                    const uint32_t* Bhf = &bh[nt >> 1][(nt & 1) * 2];
                    const uint32_t* Blf = &bl[nt >> 1][(nt & 1) * 2];
                    mma_bf16(acc[mt][nt], ah[mt], Bhf);
                    mma_bf16(acc[mt][nt], ah[mt], Blf);
                    mma_bf16(acc[mt][nt], al[mt], Bhf);
                }
        }
        __syncthreads();
    }

    // ---- epilogue ----
    int gid = lane >> 2, tig = lane & 3;
    #pragma unroll
    for (int mt = 0; mt < 2; mt++) {
        int r0 = row0 + warp_m * 32 + mt * 16 + gid;
        #pragma unroll
        for (int nt = 0; nt < 8; nt++) {
            int cc = col0 + warp_n * 64 + nt * 8 + tig * 2;
            float2 v0 = make_float2(acc[mt][nt][0], acc[mt][nt][1]);
            float2 v1 = make_float2(acc[mt][nt][2], acc[mt][nt][3]);
            if (mode == 2) {
                float bx = bias[cc], by = bias[cc + 1];
                v0.x = fmaxf(v0.x + bx, 0.f); v0.y = fmaxf(v0.y + by, 0.f);
                v1.x = fmaxf(v1.x + bx, 0.f); v1.y = fmaxf(v1.y + by, 0.f);
                uint32_t h0, l0, h1, l1;
                split2(v0.x, v0.y, h0, l0);
                split2(v1.x, v1.y, h1, l1);
                if (r0 < M) {
                    *(uint32_t*)&Chi[(size_t)r0 * N + cc] = h0;
                    *(uint32_t*)&Clo[(size_t)r0 * N + cc] = l0;
                }
                if (r0 + 8 < M) {
                    *(uint32_t*)&Chi[(size_t)(r0 + 8) * N + cc] = h1;
                    *(uint32_t*)&Clo[(size_t)(r0 + 8) * N + cc] = l1;
                }
            } else {
                if (r0 < M)     *(float2*)&C[(size_t)r0 * N + cc] = v0;
                if (r0 + 8 < M) *(float2*)&C[(size_t)(r0 + 8) * N + cc] = v1;
            }
        }
    }
}

// ---------------------------- SIMT SGEMM (L4) -------------------------------

template <int BN>
__global__ __launch_bounds__(16 * (BN / 8))
void k_sgemm2(const float* __restrict__ A, const float* __restrict__ B,
              float* __restrict__ C, int M, int K, int N, int relu_in) {
    const int BM = 128, BK = 16;
    const int THREADS = 16 * (BN / 8);
    const int A_PT = (BM * BK / 4) / THREADS;
    const int B_PT = (BK * BN / 4) / THREADS;

    __shared__ float As[2][BK][BM];
    __shared__ float Bs[2][BK][BN];

    int tid = threadIdx.x;
    int tx = tid % (BN / 8);
    int ty = tid / (BN / 8);
    int row0 = blockIdx.y * BM;
    int col0 = blockIdx.x * BN;
    const int nk = K / BK;

    float acc[8][8];
    #pragma unroll
    for (int i = 0; i < 8; i++)
        #pragma unroll
        for (int j = 0; j < 8; j++) acc[i][j] = 0.0f;

    float4 pa[A_PT];
    float4 pb[B_PT];

    #pragma unroll
    for (int l = 0; l < A_PT; l++) {
        int i = tid + l * THREADS;
        int r = i >> 2;
        int c4 = (i & 3) * 4;
        int gr = row0 + r;
        float4 v = make_float4(0.f, 0.f, 0.f, 0.f);
        if (gr < M) v = *(const float4*)&A[(size_t)gr * K + c4];
        if (relu_in) {
            v.x = fmaxf(v.x, 0.f); v.y = fmaxf(v.y, 0.f);
            v.z = fmaxf(v.z, 0.f); v.w = fmaxf(v.w, 0.f);
        }
        As[0][c4 + 0][r] = v.x; As[0][c4 + 1][r] = v.y;
        As[0][c4 + 2][r] = v.z; As[0][c4 + 3][r] = v.w;
    }
    #pragma unroll
    for (int l = 0; l < B_PT; l++) {
        int i = tid + l * THREADS;
        int r = i / (BN / 4);
        int c4 = (i % (BN / 4)) * 4;
        *(float4*)&Bs[0][r][c4] = *(const float4*)&B[(size_t)r * N + col0 + c4];
    }
    __syncthreads();

    for (int t = 0; t < nk; t++) {
        int p = t & 1;
        int kn = (t + 1) * BK;

        if (t + 1 < nk) {
            #pragma unroll
            for (int l = 0; l < A_PT; l++) {
                int i = tid + l * THREADS;
                int r = i >> 2;
                int c4 = (i & 3) * 4;
                int gr = row0 + r;
                float4 v = make_float4(0.f, 0.f, 0.f, 0.f);
                if (gr < M) v = *(const float4*)&A[(size_t)gr * K + kn + c4];
                if (relu_in) {
                    v.x = fmaxf(v.x, 0.f); v.y = fmaxf(v.y, 0.f);
                    v.z = fmaxf(v.z, 0.f); v.w = fmaxf(v.w, 0.f);
                }
                pa[l] = v;
            }
            #pragma unroll
            for (int l = 0; l < B_PT; l++) {
                int i = tid + l * THREADS;
                int r = i / (BN / 4);
                int c4 = (i % (BN / 4)) * 4;
                pb[l] = *(const float4*)&B[(size_t)(kn + r) * N + col0 + c4];
            }
        }

        #pragma unroll
        for (int k = 0; k < BK; k++) {
            float4 a0 = *(const float4*)&As[p][k][ty * 8];
            float4 a1 = *(const float4*)&As[p][k][ty * 8 + 4];
            float4 b0 = *(const float4*)&Bs[p][k][tx * 8];
            float4 b1 = *(const float4*)&Bs[p][k][tx * 8 + 4];
            float a[8] = {a0.x, a0.y, a0.z, a0.w, a1.x, a1.y, a1.z, a1.w};
            float b[8] = {b0.x, b0.y, b0.z, b0.w, b1.x, b1.y, b1.z, b1.w};
            #pragma unroll
            for (int i = 0; i < 8; i++)
                #pragma unroll
                for (int j = 0; j < 8; j++)
                    acc[i][j] = fmaf(a[i], b[j], acc[i][j]);
        }

        if (t + 1 < nk) {
            int q = 1 - p;
            #pragma unroll
            for (int l = 0; l < A_PT; l++) {
                int i = tid + l * THREADS;
                int r = i >> 2;
                int c4 = (i & 3) * 4;
                As[q][c4 + 0][r] = pa[l].x; As[q][c4 + 1][r] = pa[l].y;
                As[q][c4 + 2][r] = pa[l].z; As[q][c4 + 3][r] = pa[l].w;
            }
            #pragma unroll
            for (int l = 0; l < B_PT; l++) {
                int i = tid + l * THREADS;
                int r = i / (BN / 4);
                int c4 = (i % (BN / 4)) * 4;
                *(float4*)&Bs[q][r][c4] = pb[l];
            }
            __syncthreads();
        }
    }

    #pragma unroll
    for (int i = 0; i < 8; i++) {
        int gr = row0 + ty * 8 + i;
        if (gr >= M) continue;
        float4 v0 = make_float4(acc[i][0], acc[i][1], acc[i][2], acc[i][3]);
        float4 v1 = make_float4(acc[i][4], acc[i][5], acc[i][6], acc[i][7]);
        *(float4*)&C[(size_t)gr * N + col0 + tx * 8]     = v0;
        *(float4*)&C[(size_t)gr * N + col0 + tx * 8 + 4] = v1;
    }
}

// L5 matvec
__global__ void k_matvec64(const float* __restrict__ X, const float* __restrict__ W,
                           float* __restrict__ out, int M) {
    __shared__ float w[64];
    int t = threadIdx.x;
    if (t < 64) w[t] = W[t];
    __syncthreads();
    int i = blockIdx.x * blockDim.x + t;
    if (i < M) {
        const float4* xr = (const float4*)(X + (size_t)i * 64);
        float s = 0.f;
        #pragma unroll
        for (int k = 0; k < 16; k++) {
            float4 v = xr[k];
            s = fmaf(fmaxf(v.x, 0.f), w[4 * k + 0], s);
            s = fmaf(fmaxf(v.y, 0.f), w[4 * k + 1], s);
            s = fmaf(fmaxf(v.z, 0.f), w[4 * k + 2], s);
            s = fmaf(fmaxf(v.w, 0.f), w[4 * k + 3], s);
        }
        out[i] = s;
    }
}

// ---------------------------- launch ---------------------------------------

static inline unsigned blocks_for(size_t total, int threads) {
    return (unsigned)((total + threads - 1) / threads);
}

extern "C" void kernel_launch(void* const* d_in, const int* in_sizes, int n_in,
                              void* d_out, int out_size) {
    const float* x  = (const float*)d_in[0];
    const int*   ei = (const int*)d_in[1];
    const int N = in_sizes[0] / 128;
    const int E = in_sizes[1] / 2;
    const int* src = ei;
    const int* dst = ei + E;
    const float* W1 = (const float*)d_in[2];  const float* b1 = (const float*)d_in[3];
    const float* W2 = (const float*)d_in[4];  const float* b2 = (const float*)d_in[5];
    const float* W3 = (const float*)d_in[6];  const float* b3 = (const float*)d_in[7];
    const float* W4 = (const float*)d_in[8];  const float* b4 = (const float*)d_in[9];
    const float* W5 = (const float*)d_in[10]; const float* b5 = (const float*)d_in[11];
    float* out = (float*)d_out;

    float *bufA, *bufB, *dinv, *csr_nrm;
    int *cnt, *rows, *pos, *partial, *csr_src;
    __nv_bfloat16 *wthi, *wtlo, *ahi, *alo, *bhi, *blo;
    cudaGetSymbolAddress((void**)&bufA, g_bufA);
    cudaGetSymbolAddress((void**)&bufB, g_bufB);
    cudaGetSymbolAddress((void**)&dinv, g_dinv);
    cudaGetSymbolAddress((void**)&cnt, g_cnt);
    cudaGetSymbolAddress((void**)&rows, g_rows);
    cudaGetSymbolAddress((void**)&pos, g_pos);
    cudaGetSymbolAddress((void**)&partial, g_partial);
    cudaGetSymbolAddress((void**)&csr_src, g_csr_src);
    cudaGetSymbolAddress((void**)&csr_nrm, g_csr_nrm);
    cudaGetSymbolAddress((void**)&wthi, g_wthi);
    cudaGetSymbolAddress((void**)&wtlo, g_wtlo);
    cudaGetSymbolAddress((void**)&ahi, g_ahi);
    cudaGetSymbolAddress((void**)&alo, g_alo);
    cudaGetSymbolAddress((void**)&bhi, g_bhi);
    cudaGetSymbolAddress((void**)&blo, g_blo);

    cudaFuncSetAttribute(k_mma_gemm, cudaFuncAttributeMaxDynamicSharedMemorySize,
                         MMA_SMEM);

    const int T = 256;
    const int nblk = (N + 255) / 256;
    const int mtiles = (N + 127) / 128;
    const size_t Mpad = (size_t)mtiles * 128;
    const size_t npadr = Mpad - N;  // pad rows

    // ---- CSR build ----
    k_zero_cnt<<<nblk, T>>>(cnt, N);
    k_hist<<<blocks_for(E, T), T>>>(dst, cnt, E);
    k_dinv<<<nblk, T>>>(cnt, dinv, N);
    k_scan_blk<<<nblk, T>>>(cnt, rows, partial, N);
    k_scan_top<<<1, T>>>(partial, nblk);
    k_scan_add<<<nblk, T>>>(rows, pos, partial, N, E);
    k_scatter<<<blocks_for(E, T), T>>>(src, dst, dinv, pos, csr_src, csr_nrm, E);

    // ---- Layer 1: CSR-agg of x -> ahi/alo [*,128]; GEMM 128->1024
    //      epilogue (b1+relu) splits straight into bhi/blo [*,1024] ----
    k_csr_agg_split<32, 0><<<(N + 7) / 8, 256>>>(
        (const float4*)x, rows, csr_src, csr_nrm, dinv, nullptr,
        (uint2*)ahi, (uint2*)alo, N);
    k_zero_pad<<<blocks_for(npadr * 128 / 4, T), T>>>(
        (uint2*)ahi, (uint2*)alo, (size_t)N * 128 / 4, npadr * 128 / 4);
    k_wt<<<blocks_for(1024 * 128, T), T>>>(W1, wthi, wtlo, 128, 1024);
    k_mma_gemm<<<dim3(1024 / 128, mtiles), 256, MMA_SMEM>>>(
        ahi, alo, wthi, wtlo, b1, nullptr, bhi, blo, N, 128, 1024, 2);
    k_zero_pad<<<blocks_for(npadr * 1024 / 4, T), T>>>(
        (uint2*)bhi, (uint2*)blo, (size_t)N * 1024 / 4, npadr * 1024 / 4);

    // ---- Layer 2: GEMM 1024->512 (fp32 out), CSR-agg (+b2, relu)
    //      splits into ahi/alo [*,512] for L3 ----
    k_wt<<<blocks_for(512 * 1024, T), T>>>(W2, wthi, wtlo, 1024, 512);
    k_mma_gemm<<<dim3(512 / 128, mtiles), 256, MMA_SMEM>>>(
        bhi, blo, wthi, wtlo, nullptr, bufA, nullptr, nullptr, N, 1024, 512, 0);
    k_csr_agg_split<128, 1><<<(N + 1) / 2, 256>>>(
        (const float4*)bufA, rows, csr_src, csr_nrm, dinv, b2,
        (uint2*)ahi, (uint2*)alo, N);
    k_zero_pad<<<blocks_for(npadr * 512 / 4, T), T>>>(
        (uint2*)ahi, (uint2*)alo, (size_t)N * 512 / 4, npadr * 512 / 4);

    // ---- Layer 3: GEMM 512->256 (fp32 out), CSR-agg fp32 (+b3) ----
    k_wt<<<blocks_for(256 * 512, T), T>>>(W3, wthi, wtlo, 512, 256);
    k_mma_gemm<<<dim3(256 / 128, mtiles), 256, MMA_SMEM>>>(
        ahi, alo, wthi, wtlo, nullptr, bufA, nullptr, nullptr, N, 512, 256, 0);
    k_csr_agg<64><<<(N + 3) / 4, 256>>>((const float4*)bufA, rows, csr_src, csr_nrm,
                                        dinv, b3, (float4*)bufB, N);

    // ---- Layer 4: SIMT GEMM 256->64 (relu in), CSR-agg (+b4) ----
    {
        dim3 g(64 / 64, mtiles);
        k_sgemm2<64><<<g, 128>>>(bufB, W4, bufA, N, 256, 64, 1);
    }
    k_csr_agg<16><<<(N + 15) / 16, 256>>>((const float4*)bufA, rows, csr_src, csr_nrm,
                                          dinv, b4, (float4*)bufB, N);

    // ---- Layer 5: matvec 64->1 (relu in), scalar CSR-agg into out ----
    k_matvec64<<<blocks_for(N, T), T>>>(bufB, W5, bufA, N);
    k_out_scalar<<<nblk, T>>>(bufA, rows, csr_src, csr_nrm, dinv, b5, out, N);
}